// round 14
// baseline (speedup 1.0000x reference)
#include <cuda_runtime.h>
#include <cuda_bf16.h>
#include <cstdint>

#define BB 32
#define TT 64
#define NFR 2048
#define AA 6
#define LL 32
#define HH 128
#define FD 256

// ---------------- static device scratch ----------------
__device__ float g_b1[(size_t)NFR * 32 * 32 * 32];
__device__ float g_b2[(size_t)NFR * 64 * 16 * 16];
__device__ float g_b3[(size_t)NFR * 128 * 8 * 8];
__device__ float g_b4[(size_t)NFR * 256 * 16];
__device__ float g_feats[(size_t)NFR * FD];
// transposed scan weights: [k][j]
__device__ __align__(16) float g_wihT[38 * 384];
__device__ __align__(16) float g_whhT[128 * 384];
__device__ __align__(16) float g_pwT[128 * 64];
__device__ __align__(16) float g_qwT[384 * 64];

// ---------------- helpers ----------------
__device__ __forceinline__ uint32_t smem_u32(const void* p) {
    uint32_t a;
    asm("{ .reg .u64 t; cvta.to.shared.u64 t, %1; cvt.u32.u64 %0, t; }" : "=r"(a) : "l"(p));
    return a;
}
__device__ __forceinline__ void bsplit(float v, __nv_bfloat16& h, __nv_bfloat16& l) {
    h = __float2bfloat16(v);
    l = __float2bfloat16(v - __bfloat162float(h));
}
__device__ __forceinline__ void pack2(float v0, float v1, uint32_t& hw, uint32_t& lw) {
    __nv_bfloat16 h0, l0, h1, l1;
    bsplit(v0, h0, l0);
    bsplit(v1, h1, l1);
    hw = (uint32_t)__bfloat16_as_ushort(h0) | ((uint32_t)__bfloat16_as_ushort(h1) << 16);
    lw = (uint32_t)__bfloat16_as_ushort(l0) | ((uint32_t)__bfloat16_as_ushort(l1) << 16);
}
__device__ __forceinline__ void ldmx4(uint32_t* r, uint32_t addr) {
    asm volatile("ldmatrix.sync.aligned.m8n8.x4.shared.b16 {%0,%1,%2,%3}, [%4];"
                 : "=r"(r[0]), "=r"(r[1]), "=r"(r[2]), "=r"(r[3]) : "r"(addr));
}
__device__ __forceinline__ void mma16816(float* c, const uint32_t* a, const uint32_t* b) {
    asm volatile(
        "mma.sync.aligned.m16n8k16.row.col.f32.bf16.bf16.f32 "
        "{%0,%1,%2,%3}, {%4,%5,%6,%7}, {%8,%9}, {%0,%1,%2,%3};"
        : "+f"(c[0]), "+f"(c[1]), "+f"(c[2]), "+f"(c[3])
        : "r"(a[0]), "r"(a[1]), "r"(a[2]), "r"(a[3]), "r"(b[0]), "r"(b[1]));
}

// ---------------- scan weight transpose (after convs; before fc/scan) ----------------
struct PackScanArgs {
    const float *wih, *whh, *pw, *qw;
    float *wihT, *whhT, *pwT, *qwT;
};
__global__ void pack_scan_kernel(PackScanArgs a) {
    constexpr int S6 = 38 * 384,  C6 = S6;
    constexpr int S7 = 128 * 384, C7 = C6 + S7;
    constexpr int S8 = 128 * 64,  C8 = C7 + S8;
    constexpr int S9 = 384 * 64,  C9 = C8 + S9;
    for (int idx = blockIdx.x * blockDim.x + threadIdx.x; idx < C9;
         idx += gridDim.x * blockDim.x) {
        if (idx < C6)      { int t = idx;      int k = t / 384, j = t % 384;
                             a.wihT[t] = a.wih[(size_t)j * 38 + k]; }
        else if (idx < C7) { int t = idx - C6; int k = t / 384, j = t % 384;
                             a.whhT[t] = a.whh[(size_t)j * 128 + k]; }
        else if (idx < C8) { int t = idx - C7; int k = t / 64, j = t % 64;
                             a.pwT[t] = a.pw[(size_t)j * 128 + k]; }
        else               { int t = idx - C8; int k = t / 64, j = t % 64;
                             a.qwT[t] = a.qw[(size_t)j * 384 + k]; }
    }
}

// ---------------- pipelined tensor-core im2col GEMM (bf16 split, inline B split) -----
// B staged from RAW fp32 weights w[oc][KR]: float2 LDG (issued one MMA-phase early,
// like A) -> pack2 -> STS. A and B single-buffered; two syncs per chunk (R7 schedule).
template <int ICR, int IH, int OC, int KTOT, int KR, int NT, bool IM2COL, bool RELU, int POS>
__global__ void __launch_bounds__(256)
mmagemm_kernel(const float* __restrict__ in, const float* __restrict__ gW,
               const float* __restrict__ bias, float* __restrict__ outp) {
    constexpr int AS  = 40;
    constexpr int OW  = IH / 2;
    constexpr int WN  = NT / 2;
    constexpr int NTI = WN / 8;
    constexpr int NPAIR = WN / 16;
    constexpr int NCH = KTOT / 32;
    constexpr int GB  = NT / 16;           // B float2-pairs per thread

    extern __shared__ __align__(16) char smem[];
    __nv_bfloat16* Ah = (__nv_bfloat16*)smem;                // 128*AS
    __nv_bfloat16* Al = Ah + 128 * AS;
    __nv_bfloat16* Bh = Al + 128 * AS;                        // NT*AS
    __nv_bfloat16* Bl = Bh + NT * AS;

    const uint32_t sb   = smem_u32(smem);
    const uint32_t ah_b = sb;
    const uint32_t al_b = sb + 128 * AS * 2;
    const uint32_t bh_b = sb + 128 * AS * 4;
    const uint32_t bl_b = bh_b + NT * AS * 2;

    const int tid = threadIdx.x, lane = tid & 31, wid = tid >> 5;
    const int wm = wid & 3, wn = wid >> 2;
    const int m0 = blockIdx.x * 128;
    const int n0g = blockIdx.y * NT;

    float acc[2][NTI][4];
#pragma unroll
    for (int mt = 0; mt < 2; ++mt)
#pragma unroll
        for (int nt = 0; nt < NTI; ++nt)
#pragma unroll
            for (int q = 0; q < 4; ++q) acc[mt][nt][q] = 0.f;

    // per-thread A gather geometry
    const int r  = tid & 127;
    const int kg = tid >> 7;
    const int m  = m0 + r;
    const int fr = m / POS;
    const int pg = m & (POS - 1);
    const int oy = pg / OW, ox = pg & (OW - 1);
    const int iyb = 2 * oy - 1, ixb = 2 * ox - 1;
    // per-thread B geometry
    const int boc = tid >> 4;              // 0..15 (oc = boc + 16*g)
    const int bk2 = (tid & 15) * 2;        // k-pair within 32-chunk

    float va[16];
    float wb[2 * GB];

    auto GATHER = [&](int ch) {            // pure A loads
        if (IM2COL) {
            const int ic = ch * 2 + kg;
            const bool icok = (ic < ICR);
            const float* plane = in + ((size_t)fr * ICR + (icok ? ic : 0)) * IH * IH;
#pragma unroll
            for (int ky = 0; ky < 4; ++ky) {
                int iy = iyb + ky;
                bool yok = icok && iy >= 0 && iy < IH;
                const float* rp = plane + iy * IH;
                va[4 * ky + 0] = (yok && ixb >= 0)     ? rp[ixb]     : 0.f;
                va[4 * ky + 1] = yok                   ? rp[ixb + 1] : 0.f;
                va[4 * ky + 2] = yok                   ? rp[ixb + 2] : 0.f;
                va[4 * ky + 3] = (yok && ixb + 3 < IH) ? rp[ixb + 3] : 0.f;
            }
        } else {
            const float* rp = in + (size_t)m * KTOT + ch * 32 + kg * 16;
#pragma unroll
            for (int q = 0; q < 4; ++q) {
                float4 v = *(const float4*)(rp + q * 4);
                va[4 * q + 0] = v.x; va[4 * q + 1] = v.y;
                va[4 * q + 2] = v.z; va[4 * q + 3] = v.w;
            }
        }
    };
    auto LDGB = [&](int ch) {              // pure B loads (raw fp32 weights)
        const int k = ch * 32 + bk2;
#pragma unroll
        for (int g = 0; g < GB; ++g) {
            int oc = n0g + boc + 16 * g;
            float2 v = make_float2(0.f, 0.f);
            if (KR == KTOT || k < KR)
                v = *(const float2*)&gW[(size_t)oc * KR + k];
            wb[2 * g]     = v.x;
            wb[2 * g + 1] = v.y;
        }
    };
    auto STOREA = [&]() {
        uint32_t hw[8], lw[8];
#pragma unroll
        for (int q = 0; q < 8; ++q) pack2(va[2 * q], va[2 * q + 1], hw[q], lw[q]);
        uint32_t dof = r * AS + kg * 16;
        *(uint4*)&Ah[dof]     = *(uint4*)&hw[0];
        *(uint4*)&Ah[dof + 8] = *(uint4*)&hw[4];
        *(uint4*)&Al[dof]     = *(uint4*)&lw[0];
        *(uint4*)&Al[dof + 8] = *(uint4*)&lw[4];
    };
    auto STSB = [&]() {
#pragma unroll
        for (int g = 0; g < GB; ++g) {
            int oc = boc + 16 * g;
            uint32_t hw_, lw_;
            pack2(wb[2 * g], wb[2 * g + 1], hw_, lw_);
            ((uint32_t*)Bh)[oc * 20 + (bk2 >> 1)] = hw_;
            ((uint32_t*)Bl)[oc * 20 + (bk2 >> 1)] = lw_;
        }
    };

    // ---- prologue ----
    GATHER(0);
    LDGB(0);
    STOREA();
    STSB();
    if (NCH > 1) { GATHER(1); LDGB(1); }
    __syncthreads();

    for (int ch = 0; ch < NCH; ++ch) {
#pragma unroll
        for (int ks = 0; ks < 32; ks += 16) {
            uint32_t ahf[2][4], alf[2][4];
#pragma unroll
            for (int mt = 0; mt < 2; ++mt) {
                int row = wm * 32 + mt * 16 + (lane & 15);
                int koff = ks + ((lane >> 4) << 3);
                uint32_t off = (uint32_t)(row * AS + koff) * 2;
                ldmx4(ahf[mt], ah_b + off);
                ldmx4(alf[mt], al_b + off);
            }
#pragma unroll
            for (int np = 0; np < NPAIR; ++np) {
                uint32_t bhf[4], blf[4];
                int n = wn * WN + np * 16 + (lane & 7) + ((lane >> 4) << 3);
                int koff = ks + (((lane >> 3) & 1) << 3);
                uint32_t off = (uint32_t)(n * AS + koff) * 2;
                ldmx4(bhf, bh_b + off);
                ldmx4(blf, bl_b + off);
#pragma unroll
                for (int s = 0; s < 2; ++s) {
                    int nt = np * 2 + s;
#pragma unroll
                    for (int mt = 0; mt < 2; ++mt) {
                        mma16816(acc[mt][nt], ahf[mt], bhf + 2 * s);
                        mma16816(acc[mt][nt], ahf[mt], blf + 2 * s);
                        mma16816(acc[mt][nt], alf[mt], bhf + 2 * s);
                    }
                }
            }
        }
        __syncthreads();                  // smem reads done
        if (ch + 1 < NCH) {
            STOREA();                     // va/wb hold chunk ch+1
            STSB();
            if (ch + 2 < NCH) { GATHER(ch + 2); LDGB(ch + 2); }  // fly under MMA(ch+1)
            __syncthreads();              // stores visible
        }
    }

    // ---- epilogue ----
#pragma unroll
    for (int mt = 0; mt < 2; ++mt) {
#pragma unroll
        for (int nt = 0; nt < NTI; ++nt) {
            int oc = n0g + wn * WN + nt * 8 + 2 * (lane & 3);
            float b0 = bias[oc], b1 = bias[oc + 1];
#pragma unroll
            for (int half = 0; half < 2; ++half) {
                int mm = m0 + wm * 32 + mt * 16 + (lane >> 2) + half * 8;
                float x0 = acc[mt][nt][2 * half]     + b0;
                float x1 = acc[mt][nt][2 * half + 1] + b1;
                if (RELU) { x0 = fmaxf(x0, 0.f); x1 = fmaxf(x1, 0.f); }
                if (IM2COL) {
                    int frr = mm / POS;
                    int pgg = mm & (POS - 1);
                    size_t base = ((size_t)frr * OC + oc) * POS + pgg;
                    outp[base]       = x0;
                    outp[base + POS] = x1;
                } else {
                    *(float2*)&outp[(size_t)mm * OC + oc] = make_float2(x0, x1);
                }
            }
        }
    }
}

// ---------------- sequential scan (coalesced transposed weights) ----------------
__global__ void scan_kernel(const float* __restrict__ actions, const float* __restrict__ feats,
                            const float* __restrict__ wihT, const float* __restrict__ whhT,
                            const float* __restrict__ bih, const float* __restrict__ bhh,
                            const float* __restrict__ pwT, const float* __restrict__ pb,
                            const float* __restrict__ qwT, const float* __restrict__ qb,
                            const float* __restrict__ eps, float* __restrict__ out) {
    int b = blockIdx.x, tid = threadIdx.x;
    __shared__ float x_s[40];
    __shared__ __align__(16) float h_s[HH];
    __shared__ __align__(16) float f_s[FD];
    __shared__ float gi_s[3 * HH], gh_s[3 * HH];
    __shared__ float p_s[2 * LL], q_s[2 * LL];

    if (tid < LL + AA) x_s[tid] = 0.f;
    if (tid < HH) h_s[tid] = 0.f;

    const float bih_j = bih[tid];
    const float bhh_j = bhh[tid];

    float* out_mup = out;
    float* out_lvp = out + (size_t)NFR * LL;
    float* out_muq = out + (size_t)NFR * LL * 2;
    float* out_lvq = out + (size_t)NFR * LL * 3;
    float* out_h   = out + (size_t)NFR * LL * 4;
    float* out_z   = out + (size_t)NFR * LL * 4 + (size_t)NFR * HH;

    for (int t = 0; t < TT; ++t) {
        int bt = b * TT + t;
        if (tid >= LL && tid < LL + AA) x_s[tid] = actions[(size_t)bt * AA + (tid - LL)];
        if (tid < FD) f_s[tid] = feats[(size_t)bt * FD + tid];
        __syncthreads();

        {
            const int j = tid;
            float a0 = 0.f, a1 = 0.f;
#pragma unroll
            for (int k = 0; k < 38; k += 2) {
                a0 = fmaf(x_s[k],     wihT[(size_t)k * 384 + j],       a0);
                a1 = fmaf(x_s[k + 1], wihT[(size_t)(k + 1) * 384 + j], a1);
            }
            float g0 = 0.f, g1 = 0.f, g2 = 0.f, g3 = 0.f;
#pragma unroll
            for (int k = 0; k < HH; k += 4) {
                g0 = fmaf(h_s[k],     whhT[(size_t)k * 384 + j],       g0);
                g1 = fmaf(h_s[k + 1], whhT[(size_t)(k + 1) * 384 + j], g1);
                g2 = fmaf(h_s[k + 2], whhT[(size_t)(k + 2) * 384 + j], g2);
                g3 = fmaf(h_s[k + 3], whhT[(size_t)(k + 3) * 384 + j], g3);
            }
            gi_s[j] = bih_j + a0 + a1;
            gh_s[j] = bhh_j + (g0 + g1) + (g2 + g3);
        }
        __syncthreads();

        if (tid < HH) {
            int u = tid;
            float r  = 1.f / (1.f + expf(-(gi_s[u] + gh_s[u])));
            float zz = 1.f / (1.f + expf(-(gi_s[u + HH] + gh_s[u + HH])));
            float nn = tanhf(gi_s[u + 2 * HH] + r * gh_s[u + 2 * HH]);
            h_s[u] = (1.f - zz) * nn + zz * h_s[u];
        }
        __syncthreads();

        if (tid < 2 * LL) {
            const int j = tid;
            float g0 = 0.f, g1 = 0.f, g2 = 0.f, g3 = 0.f;
#pragma unroll
            for (int k = 0; k < HH; k += 4) {
                g0 = fmaf(h_s[k],     pwT[(size_t)k * 64 + j],       g0);
                g1 = fmaf(h_s[k + 1], pwT[(size_t)(k + 1) * 64 + j], g1);
                g2 = fmaf(h_s[k + 2], pwT[(size_t)(k + 2) * 64 + j], g2);
                g3 = fmaf(h_s[k + 3], pwT[(size_t)(k + 3) * 64 + j], g3);
            }
            p_s[j] = pb[j] + (g0 + g1) + (g2 + g3);
        } else if (tid < 4 * LL) {
            const int j = tid - 2 * LL;
            float g0 = 0.f, g1 = 0.f, g2 = 0.f, g3 = 0.f;
#pragma unroll
            for (int k = 0; k < HH; k += 4) {
                g0 = fmaf(h_s[k],     qwT[(size_t)k * 64 + j],       g0);
                g1 = fmaf(h_s[k + 1], qwT[(size_t)(k + 1) * 64 + j], g1);
                g2 = fmaf(h_s[k + 2], qwT[(size_t)(k + 2) * 64 + j], g2);
                g3 = fmaf(h_s[k + 3], qwT[(size_t)(k + 3) * 64 + j], g3);
            }
#pragma unroll
            for (int k = 0; k < FD; k += 4) {
                g0 = fmaf(f_s[k],     qwT[(size_t)(HH + k) * 64 + j],     g0);
                g1 = fmaf(f_s[k + 1], qwT[(size_t)(HH + k + 1) * 64 + j], g1);
                g2 = fmaf(f_s[k + 2], qwT[(size_t)(HH + k + 2) * 64 + j], g2);
                g3 = fmaf(f_s[k + 3], qwT[(size_t)(HH + k + 3) * 64 + j], g3);
            }
            q_s[j] = qb[j] + (g0 + g1) + (g2 + g3);
        }
        __syncthreads();

        if (tid < HH) out_h[(size_t)bt * HH + tid] = h_s[tid];
        if (tid < LL) {
            int l = tid;
            out_mup[(size_t)bt * LL + l] = p_s[l];
            out_lvp[(size_t)bt * LL + l] = p_s[l + LL];
            float muq = q_s[l], lvq = q_s[l + LL];
            out_muq[(size_t)bt * LL + l] = muq;
            out_lvq[(size_t)bt * LL + l] = lvq;
            float z = muq + expf(0.5f * lvq) * eps[(size_t)bt * LL + l];
            out_z[(size_t)bt * LL + l] = z;
            x_s[l] = z;
        }
        __syncthreads();
    }
}

// ---------------- launch ----------------
extern "C" void kernel_launch(void* const* d_in, const int* in_sizes, int n_in,
                              void* d_out, int out_size) {
    const float* states  = (const float*)d_in[0];
    const float* actions = (const float*)d_in[1];
    const float* c1_w = (const float*)d_in[2];
    const float* c1_b = (const float*)d_in[3];
    const float* c2_w = (const float*)d_in[4];
    const float* c2_b = (const float*)d_in[5];
    const float* c3_w = (const float*)d_in[6];
    const float* c3_b = (const float*)d_in[7];
    const float* c4_w = (const float*)d_in[8];
    const float* c4_b = (const float*)d_in[9];
    const float* fc_w = (const float*)d_in[10];
    const float* fc_b = (const float*)d_in[11];
    const float* gru_wih = (const float*)d_in[12];
    const float* gru_whh = (const float*)d_in[13];
    const float* gru_bih = (const float*)d_in[14];
    const float* gru_bhh = (const float*)d_in[15];
    const float* prior_w = (const float*)d_in[16];
    const float* prior_b = (const float*)d_in[17];
    const float* post_w  = (const float*)d_in[18];
    const float* post_b  = (const float*)d_in[19];
    const float* eps     = (const float*)d_in[20];
    float* out = (float*)d_out;

    float *b1, *b2, *b3, *b4, *feats, *wihT, *whhT, *pwT, *qwT;
    cudaGetSymbolAddress((void**)&b1, g_b1);
    cudaGetSymbolAddress((void**)&b2, g_b2);
    cudaGetSymbolAddress((void**)&b3, g_b3);
    cudaGetSymbolAddress((void**)&b4, g_b4);
    cudaGetSymbolAddress((void**)&feats, g_feats);
    cudaGetSymbolAddress((void**)&wihT, g_wihT);
    cudaGetSymbolAddress((void**)&whhT, g_whhT);
    cudaGetSymbolAddress((void**)&pwT, g_pwT);
    cudaGetSymbolAddress((void**)&qwT, g_qwT);

    // <ICR, IH, OC, KTOT, KR, NT, IM2COL, RELU, POS>
    auto c1 = mmagemm_kernel<3, 64, 32, 64, 48, 32, true, true, 1024>;
    auto c2 = mmagemm_kernel<32, 32, 64, 512, 512, 64, true, true, 256>;
    auto c3 = mmagemm_kernel<64, 16, 128, 1024, 1024, 128, true, true, 64>;
    auto c4 = mmagemm_kernel<128, 8, 256, 2048, 2048, 128, true, true, 16>;
    auto fc = mmagemm_kernel<1, 2, 256, 4096, 4096, 128, false, false, 1>;
    const int smA = 128 * 40 * 2 * 2;                  // 20480
    const int sm1 = smA + 32 * 40 * 2 * 2;             // 25600
    const int sm2 = smA + 64 * 40 * 2 * 2;             // 30720
    const int sm3 = smA + 128 * 40 * 2 * 2;            // 40960
    cudaFuncSetAttribute(c1, cudaFuncAttributeMaxDynamicSharedMemorySize, sm1);
    cudaFuncSetAttribute(c2, cudaFuncAttributeMaxDynamicSharedMemorySize, sm2);
    cudaFuncSetAttribute(c3, cudaFuncAttributeMaxDynamicSharedMemorySize, sm3);
    cudaFuncSetAttribute(c4, cudaFuncAttributeMaxDynamicSharedMemorySize, sm3);
    cudaFuncSetAttribute(fc, cudaFuncAttributeMaxDynamicSharedMemorySize, sm3);

    // 0: conv1 GEMM (M=2097152, N=32, K=64, inline B split)
    c1<<<dim3(16384, 1), 256, sm1>>>(states, c1_w, c1_b, b1);
    // 1: conv2 GEMM (M=524288, N=64, K=512)
    c2<<<dim3(4096, 1), 256, sm2>>>(b1, c2_w, c2_b, b2);
    // 2: conv3 GEMM (M=131072, N=128, K=1024)
    c3<<<dim3(1024, 1), 256, sm3>>>(b2, c3_w, c3_b, b3);
    // 3 <- profiled: conv4 GEMM (M=32768, N=256, K=2048)
    c4<<<dim3(256, 2), 256, sm3>>>(b3, c4_w, c4_b, b4);
    // 4: scan weight transposes
    PackScanArgs ps;
    ps.wih = gru_wih; ps.whh = gru_whh; ps.pw = prior_w; ps.qw = post_w;
    ps.wihT = wihT; ps.whhT = whhT; ps.pwT = pwT; ps.qwT = qwT;
    pack_scan_kernel<<<256, 256>>>(ps);
    // 5: fc GEMM (M=2048, N=256, K=4096)
    fc<<<dim3(16, 2), 256, sm3>>>(b4, fc_w, fc_b, feats);
    // 6: scan
    scan_kernel<<<BB, 384>>>(actions, feats, wihT, whhT, gru_bih, gru_bhh,
                             pwT, prior_b, qwT, post_b, eps, out);
}

// round 15
// speedup vs baseline: 1.8807x; 1.8807x over previous
#include <cuda_runtime.h>
#include <cuda_bf16.h>
#include <cstdint>

#define BB 32
#define TT 64
#define NFR 2048
#define AA 6
#define LL 32
#define HH 128
#define FD 256

// ---------------- static device scratch ----------------
__device__ float g_b1[(size_t)NFR * 32 * 32 * 32];
__device__ float g_b2[(size_t)NFR * 64 * 16 * 16];
__device__ float g_b3[(size_t)NFR * 128 * 8 * 8];
__device__ float g_b4[(size_t)NFR * 256 * 16];
__device__ float g_feats[(size_t)NFR * FD];
// bf16 hi/lo weight images, [oc][Kpad] row-major
__device__ __align__(16) __nv_bfloat16 g_w1h[32 * 64],    g_w1l[32 * 64];
__device__ __align__(16) __nv_bfloat16 g_w2h[64 * 512],   g_w2l[64 * 512];
__device__ __align__(16) __nv_bfloat16 g_w3h[128 * 1024], g_w3l[128 * 1024];
__device__ __align__(16) __nv_bfloat16 g_w4h[256 * 2048], g_w4l[256 * 2048];
__device__ __align__(16) __nv_bfloat16 g_wfh[256 * 4096], g_wfl[256 * 4096];
// transposed scan weights: [k][j]
__device__ __align__(16) float g_wihT[38 * 384];
__device__ __align__(16) float g_whhT[128 * 384];
__device__ __align__(16) float g_pwT[128 * 64];
__device__ __align__(16) float g_qwT[384 * 64];

// ---------------- helpers ----------------
__device__ __forceinline__ uint32_t smem_u32(const void* p) {
    uint32_t a;
    asm("{ .reg .u64 t; cvta.to.shared.u64 t, %1; cvt.u32.u64 %0, t; }" : "=r"(a) : "l"(p));
    return a;
}
__device__ __forceinline__ void bsplit(float v, __nv_bfloat16& h, __nv_bfloat16& l) {
    h = __float2bfloat16(v);
    l = __float2bfloat16(v - __bfloat162float(h));
}
__device__ __forceinline__ void pack2(float v0, float v1, uint32_t& hw, uint32_t& lw) {
    __nv_bfloat16 h0, l0, h1, l1;
    bsplit(v0, h0, l0);
    bsplit(v1, h1, l1);
    hw = (uint32_t)__bfloat16_as_ushort(h0) | ((uint32_t)__bfloat16_as_ushort(h1) << 16);
    lw = (uint32_t)__bfloat16_as_ushort(l0) | ((uint32_t)__bfloat16_as_ushort(l1) << 16);
}
__device__ __forceinline__ void ldmx4(uint32_t* r, uint32_t addr) {
    asm volatile("ldmatrix.sync.aligned.m8n8.x4.shared.b16 {%0,%1,%2,%3}, [%4];"
                 : "=r"(r[0]), "=r"(r[1]), "=r"(r[2]), "=r"(r[3]) : "r"(addr));
}
__device__ __forceinline__ void mma16816(float* c, const uint32_t* a, const uint32_t* b) {
    asm volatile(
        "mma.sync.aligned.m16n8k16.row.col.f32.bf16.bf16.f32 "
        "{%0,%1,%2,%3}, {%4,%5,%6,%7}, {%8,%9}, {%0,%1,%2,%3};"
        : "+f"(c[0]), "+f"(c[1]), "+f"(c[2]), "+f"(c[3])
        : "r"(a[0]), "r"(a[1]), "r"(a[2]), "r"(a[3]), "r"(b[0]), "r"(b[1]));
}
__device__ __forceinline__ void cpasync16(uint32_t dst, const void* src) {
    asm volatile("cp.async.ca.shared.global [%0], [%1], 16;" :: "r"(dst), "l"(src));
}
#define CP_COMMIT() asm volatile("cp.async.commit_group;" ::: "memory")
#define CP_WAIT0()  asm volatile("cp.async.wait_group 0;" ::: "memory")

// ---------------- merged weight pack/transpose (ONE launch) ----------------
struct PackArgs {
    const float *w1, *w2, *w3, *w4, *wf, *wih, *whh, *pw, *qw;
    __nv_bfloat16 *w1h, *w1l, *w2h, *w2l, *w3h, *w3l, *w4h, *w4l, *wfh, *wfl;
    float *wihT, *whhT, *pwT, *qwT;
};
__device__ __forceinline__ void pack_one(const float* w, __nv_bfloat16* bh,
                                         __nv_bfloat16* bl, int idx, int Kr, int Kp) {
    int oc = idx / Kp, k = idx % Kp;
    float v = (k < Kr) ? w[(size_t)oc * Kr + k] : 0.f;
    __nv_bfloat16 h, l;
    bsplit(v, h, l);
    bh[idx] = h;
    bl[idx] = l;
}
__global__ void pack_all_kernel(PackArgs a) {
    constexpr int S1 = 32 * 64,       C1 = S1;
    constexpr int S2 = 64 * 512,      C2 = C1 + S2;
    constexpr int S3 = 128 * 1024,    C3 = C2 + S3;
    constexpr int S4 = 256 * 2048,    C4 = C3 + S4;
    constexpr int S5 = 256 * 4096,    C5 = C4 + S5;
    constexpr int S6 = 38 * 384,      C6 = C5 + S6;
    constexpr int S7 = 128 * 384,     C7 = C6 + S7;
    constexpr int S8 = 128 * 64,      C8 = C7 + S8;
    constexpr int S9 = 384 * 64,      C9 = C8 + S9;
    for (int idx = blockIdx.x * blockDim.x + threadIdx.x; idx < C9;
         idx += gridDim.x * blockDim.x) {
        if (idx < C1)      pack_one(a.w1, a.w1h, a.w1l, idx, 48, 64);
        else if (idx < C2) pack_one(a.w2, a.w2h, a.w2l, idx - C1, 512, 512);
        else if (idx < C3) pack_one(a.w3, a.w3h, a.w3l, idx - C2, 1024, 1024);
        else if (idx < C4) pack_one(a.w4, a.w4h, a.w4l, idx - C3, 2048, 2048);
        else if (idx < C5) pack_one(a.wf, a.wfh, a.wfl, idx - C4, 4096, 4096);
        else if (idx < C6) { int t = idx - C5; int k = t / 384, j = t % 384;
                             a.wihT[t] = a.wih[(size_t)j * 38 + k]; }
        else if (idx < C7) { int t = idx - C6; int k = t / 384, j = t % 384;
                             a.whhT[t] = a.whh[(size_t)j * 128 + k]; }
        else if (idx < C8) { int t = idx - C7; int k = t / 64, j = t % 64;
                             a.pwT[t] = a.pw[(size_t)j * 128 + k]; }
        else               { int t = idx - C8; int k = t / 64, j = t % 64;
                             a.qwT[t] = a.qw[(size_t)j * 384 + k]; }
    }
}

// ---------------- pipelined tensor-core im2col GEMM (bf16 split, mma.sync) -----------
template <int ICR, int IH, int OC, int KTOT, int NT, bool IM2COL, bool RELU, int POS>
__global__ void __launch_bounds__(256)
mmagemm_kernel(const float* __restrict__ in, const __nv_bfloat16* __restrict__ gBh,
               const __nv_bfloat16* __restrict__ gBl, const float* __restrict__ bias,
               float* __restrict__ outp) {
    constexpr int AS  = 40;
    constexpr int OW  = IH / 2;
    constexpr int WN  = NT / 2;
    constexpr int NTI = WN / 8;
    constexpr int NPAIR = WN / 16;
    constexpr int NCH = KTOT / 32;
    constexpr uint32_t BBUF = NT * AS * 2 * 2;

    extern __shared__ __align__(16) char smem[];
    __nv_bfloat16* Ah = (__nv_bfloat16*)smem;
    __nv_bfloat16* Al = Ah + 128 * AS;

    const uint32_t sb   = smem_u32(smem);
    const uint32_t ah_b = sb;
    const uint32_t al_b = sb + 128 * AS * 2;
    const uint32_t bbase = sb + 128 * AS * 4;

    const int tid = threadIdx.x, lane = tid & 31, wid = tid >> 5;
    const int wm = wid & 3, wn = wid >> 2;
    const int m0 = blockIdx.x * 128;
    const int n0g = blockIdx.y * NT;

    float acc[2][NTI][4];
#pragma unroll
    for (int mt = 0; mt < 2; ++mt)
#pragma unroll
        for (int nt = 0; nt < NTI; ++nt)
#pragma unroll
            for (int q = 0; q < 4; ++q) acc[mt][nt][q] = 0.f;

    const int r  = tid & 127;
    const int kg = tid >> 7;
    const int m  = m0 + r;
    const int fr = m / POS;
    const int pg = m & (POS - 1);
    const int oy = pg / OW, ox = pg & (OW - 1);
    const int iyb = 2 * oy - 1, ixb = 2 * ox - 1;

    float va[16];

    auto GATHER = [&](int ch) {
        if (IM2COL) {
            const int ic = ch * 2 + kg;
            const bool icok = (ic < ICR);
            const float* plane = in + ((size_t)fr * ICR + (icok ? ic : 0)) * IH * IH;
#pragma unroll
            for (int ky = 0; ky < 4; ++ky) {
                int iy = iyb + ky;
                bool yok = icok && iy >= 0 && iy < IH;
                const float* rp = plane + iy * IH;
                va[4 * ky + 0] = (yok && ixb >= 0)     ? rp[ixb]     : 0.f;
                va[4 * ky + 1] = yok                   ? rp[ixb + 1] : 0.f;
                va[4 * ky + 2] = yok                   ? rp[ixb + 2] : 0.f;
                va[4 * ky + 3] = (yok && ixb + 3 < IH) ? rp[ixb + 3] : 0.f;
            }
        } else {
            const float* rp = in + (size_t)m * KTOT + ch * 32 + kg * 16;
#pragma unroll
            for (int q = 0; q < 4; ++q) {
                float4 v = *(const float4*)(rp + q * 4);
                va[4 * q + 0] = v.x; va[4 * q + 1] = v.y;
                va[4 * q + 2] = v.z; va[4 * q + 3] = v.w;
            }
        }
    };
    auto STOREA = [&]() {
        uint32_t hw[8], lw[8];
#pragma unroll
        for (int q = 0; q < 8; ++q) pack2(va[2 * q], va[2 * q + 1], hw[q], lw[q]);
        uint32_t dof = r * AS + kg * 16;
        *(uint4*)&Ah[dof]     = *(uint4*)&hw[0];
        *(uint4*)&Ah[dof + 8] = *(uint4*)&hw[4];
        *(uint4*)&Al[dof]     = *(uint4*)&lw[0];
        *(uint4*)&Al[dof + 8] = *(uint4*)&lw[4];
    };
    auto STAGEB = [&](int ch) {
        uint32_t bd = bbase + (ch & 1) * BBUF;
        for (int i = tid; i < NT * 4; i += 256) {
            int n = i >> 2, q = i & 3;
            size_t go = (size_t)(n0g + n) * KTOT + ch * 32 + q * 8;
            cpasync16(bd + n * 80 + q * 16, gBh + go);
            cpasync16(bd + NT * 80 + n * 80 + q * 16, gBl + go);
        }
    };

    GATHER(0);
    STAGEB(0);
    CP_COMMIT();
    STOREA();
    if (NCH > 1) GATHER(1);
    CP_WAIT0();
    __syncthreads();

    for (int ch = 0; ch < NCH; ++ch) {
        if (ch + 1 < NCH) STAGEB(ch + 1);
        CP_COMMIT();

        const uint32_t bh_b = bbase + (ch & 1) * BBUF;
        const uint32_t bl_b = bh_b + NT * 80;
#pragma unroll
        for (int ks = 0; ks < 32; ks += 16) {
            uint32_t ahf[2][4], alf[2][4];
#pragma unroll
            for (int mt = 0; mt < 2; ++mt) {
                int row = wm * 32 + mt * 16 + (lane & 15);
                int koff = ks + ((lane >> 4) << 3);
                uint32_t off = (uint32_t)(row * AS + koff) * 2;
                ldmx4(ahf[mt], ah_b + off);
                ldmx4(alf[mt], al_b + off);
            }
#pragma unroll
            for (int np = 0; np < NPAIR; ++np) {
                uint32_t bhf[4], blf[4];
                int n = wn * WN + np * 16 + (lane & 7) + ((lane >> 4) << 3);
                int koff = ks + (((lane >> 3) & 1) << 3);
                uint32_t off = (uint32_t)(n * AS + koff) * 2;
                ldmx4(bhf, bh_b + off);
                ldmx4(blf, bl_b + off);
#pragma unroll
                for (int s = 0; s < 2; ++s) {
                    int nt = np * 2 + s;
#pragma unroll
                    for (int mt = 0; mt < 2; ++mt) {
                        mma16816(acc[mt][nt], ahf[mt], bhf + 2 * s);
                        mma16816(acc[mt][nt], ahf[mt], blf + 2 * s);
                        mma16816(acc[mt][nt], alf[mt], bhf + 2 * s);
                    }
                }
            }
        }
        __syncthreads();
        if (ch + 1 < NCH) {
            STOREA();
            if (ch + 2 < NCH) GATHER(ch + 2);
            CP_WAIT0();
            __syncthreads();
        }
    }

#pragma unroll
    for (int mt = 0; mt < 2; ++mt) {
#pragma unroll
        for (int nt = 0; nt < NTI; ++nt) {
            int oc = n0g + wn * WN + nt * 8 + 2 * (lane & 3);
            float b0 = bias[oc], b1 = bias[oc + 1];
#pragma unroll
            for (int half = 0; half < 2; ++half) {
                int mm = m0 + wm * 32 + mt * 16 + (lane >> 2) + half * 8;
                float x0 = acc[mt][nt][2 * half]     + b0;
                float x1 = acc[mt][nt][2 * half + 1] + b1;
                if (RELU) { x0 = fmaxf(x0, 0.f); x1 = fmaxf(x1, 0.f); }
                if (IM2COL) {
                    int frr = mm / POS;
                    int pgg = mm & (POS - 1);
                    size_t base = ((size_t)frr * OC + oc) * POS + pgg;
                    outp[base]       = x0;
                    outp[base + POS] = x1;
                } else {
                    *(float2*)&outp[(size_t)mm * OC + oc] = make_float2(x0, x1);
                }
            }
        }
    }
}

// ---------------- sequential scan (coalesced transposed weights) ----------------
__global__ void scan_kernel(const float* __restrict__ actions, const float* __restrict__ feats,
                            const float* __restrict__ wihT, const float* __restrict__ whhT,
                            const float* __restrict__ bih, const float* __restrict__ bhh,
                            const float* __restrict__ pwT, const float* __restrict__ pb,
                            const float* __restrict__ qwT, const float* __restrict__ qb,
                            const float* __restrict__ eps, float* __restrict__ out) {
    int b = blockIdx.x, tid = threadIdx.x;
    __shared__ float x_s[40];
    __shared__ __align__(16) float h_s[HH];
    __shared__ __align__(16) float f_s[FD];
    __shared__ float gi_s[3 * HH], gh_s[3 * HH];
    __shared__ float p_s[2 * LL], q_s[2 * LL];

    if (tid < LL + AA) x_s[tid] = 0.f;
    if (tid < HH) h_s[tid] = 0.f;

    const float bih_j = bih[tid];
    const float bhh_j = bhh[tid];

    float* out_mup = out;
    float* out_lvp = out + (size_t)NFR * LL;
    float* out_muq = out + (size_t)NFR * LL * 2;
    float* out_lvq = out + (size_t)NFR * LL * 3;
    float* out_h   = out + (size_t)NFR * LL * 4;
    float* out_z   = out + (size_t)NFR * LL * 4 + (size_t)NFR * HH;

    for (int t = 0; t < TT; ++t) {
        int bt = b * TT + t;
        if (tid >= LL && tid < LL + AA) x_s[tid] = actions[(size_t)bt * AA + (tid - LL)];
        if (tid < FD) f_s[tid] = feats[(size_t)bt * FD + tid];
        __syncthreads();

        {
            const int j = tid;
            float a0 = 0.f, a1 = 0.f;
#pragma unroll
            for (int k = 0; k < 38; k += 2) {
                a0 = fmaf(x_s[k],     wihT[(size_t)k * 384 + j],       a0);
                a1 = fmaf(x_s[k + 1], wihT[(size_t)(k + 1) * 384 + j], a1);
            }
            float g0 = 0.f, g1 = 0.f, g2 = 0.f, g3 = 0.f;
#pragma unroll
            for (int k = 0; k < HH; k += 4) {
                g0 = fmaf(h_s[k],     whhT[(size_t)k * 384 + j],       g0);
                g1 = fmaf(h_s[k + 1], whhT[(size_t)(k + 1) * 384 + j], g1);
                g2 = fmaf(h_s[k + 2], whhT[(size_t)(k + 2) * 384 + j], g2);
                g3 = fmaf(h_s[k + 3], whhT[(size_t)(k + 3) * 384 + j], g3);
            }
            gi_s[j] = bih_j + a0 + a1;
            gh_s[j] = bhh_j + (g0 + g1) + (g2 + g3);
        }
        __syncthreads();

        if (tid < HH) {
            int u = tid;
            float r  = 1.f / (1.f + expf(-(gi_s[u] + gh_s[u])));
            float zz = 1.f / (1.f + expf(-(gi_s[u + HH] + gh_s[u + HH])));
            float nn = tanhf(gi_s[u + 2 * HH] + r * gh_s[u + 2 * HH]);
            h_s[u] = (1.f - zz) * nn + zz * h_s[u];
        }
        __syncthreads();

        if (tid < 2 * LL) {
            const int j = tid;
            float g0 = 0.f, g1 = 0.f, g2 = 0.f, g3 = 0.f;
#pragma unroll
            for (int k = 0; k < HH; k += 4) {
                g0 = fmaf(h_s[k],     pwT[(size_t)k * 64 + j],       g0);
                g1 = fmaf(h_s[k + 1], pwT[(size_t)(k + 1) * 64 + j], g1);
                g2 = fmaf(h_s[k + 2], pwT[(size_t)(k + 2) * 64 + j], g2);
                g3 = fmaf(h_s[k + 3], pwT[(size_t)(k + 3) * 64 + j], g3);
            }
            p_s[j] = pb[j] + (g0 + g1) + (g2 + g3);
        } else if (tid < 4 * LL) {
            const int j = tid - 2 * LL;
            float g0 = 0.f, g1 = 0.f, g2 = 0.f, g3 = 0.f;
#pragma unroll
            for (int k = 0; k < HH; k += 4) {
                g0 = fmaf(h_s[k],     qwT[(size_t)k * 64 + j],       g0);
                g1 = fmaf(h_s[k + 1], qwT[(size_t)(k + 1) * 64 + j], g1);
                g2 = fmaf(h_s[k + 2], qwT[(size_t)(k + 2) * 64 + j], g2);
                g3 = fmaf(h_s[k + 3], qwT[(size_t)(k + 3) * 64 + j], g3);
            }
#pragma unroll
            for (int k = 0; k < FD; k += 4) {
                g0 = fmaf(f_s[k],     qwT[(size_t)(HH + k) * 64 + j],     g0);
                g1 = fmaf(f_s[k + 1], qwT[(size_t)(HH + k + 1) * 64 + j], g1);
                g2 = fmaf(f_s[k + 2], qwT[(size_t)(HH + k + 2) * 64 + j], g2);
                g3 = fmaf(f_s[k + 3], qwT[(size_t)(HH + k + 3) * 64 + j], g3);
            }
            q_s[j] = qb[j] + (g0 + g1) + (g2 + g3);
        }
        __syncthreads();

        if (tid < HH) out_h[(size_t)bt * HH + tid] = h_s[tid];
        if (tid < LL) {
            int l = tid;
            out_mup[(size_t)bt * LL + l] = p_s[l];
            out_lvp[(size_t)bt * LL + l] = p_s[l + LL];
            float muq = q_s[l], lvq = q_s[l + LL];
            out_muq[(size_t)bt * LL + l] = muq;
            out_lvq[(size_t)bt * LL + l] = lvq;
            float z = muq + expf(0.5f * lvq) * eps[(size_t)bt * LL + l];
            out_z[(size_t)bt * LL + l] = z;
            x_s[l] = z;
        }
        __syncthreads();
    }
}

// ---------------- launch ----------------
extern "C" void kernel_launch(void* const* d_in, const int* in_sizes, int n_in,
                              void* d_out, int out_size) {
    const float* states  = (const float*)d_in[0];
    const float* actions = (const float*)d_in[1];
    const float* c1_w = (const float*)d_in[2];
    const float* c1_b = (const float*)d_in[3];
    const float* c2_w = (const float*)d_in[4];
    const float* c2_b = (const float*)d_in[5];
    const float* c3_w = (const float*)d_in[6];
    const float* c3_b = (const float*)d_in[7];
    const float* c4_w = (const float*)d_in[8];
    const float* c4_b = (const float*)d_in[9];
    const float* fc_w = (const float*)d_in[10];
    const float* fc_b = (const float*)d_in[11];
    const float* gru_wih = (const float*)d_in[12];
    const float* gru_whh = (const float*)d_in[13];
    const float* gru_bih = (const float*)d_in[14];
    const float* gru_bhh = (const float*)d_in[15];
    const float* prior_w = (const float*)d_in[16];
    const float* prior_b = (const float*)d_in[17];
    const float* post_w  = (const float*)d_in[18];
    const float* post_b  = (const float*)d_in[19];
    const float* eps     = (const float*)d_in[20];
    float* out = (float*)d_out;

    float *b1, *b2, *b3, *b4, *feats, *wihT, *whhT, *pwT, *qwT;
    __nv_bfloat16 *w1h, *w1l, *w2h, *w2l, *w3h, *w3l, *w4h, *w4l, *wfh, *wfl;
    cudaGetSymbolAddress((void**)&b1, g_b1);
    cudaGetSymbolAddress((void**)&b2, g_b2);
    cudaGetSymbolAddress((void**)&b3, g_b3);
    cudaGetSymbolAddress((void**)&b4, g_b4);
    cudaGetSymbolAddress((void**)&feats, g_feats);
    cudaGetSymbolAddress((void**)&w1h, g_w1h);  cudaGetSymbolAddress((void**)&w1l, g_w1l);
    cudaGetSymbolAddress((void**)&w2h, g_w2h);  cudaGetSymbolAddress((void**)&w2l, g_w2l);
    cudaGetSymbolAddress((void**)&w3h, g_w3h);  cudaGetSymbolAddress((void**)&w3l, g_w3l);
    cudaGetSymbolAddress((void**)&w4h, g_w4h);  cudaGetSymbolAddress((void**)&w4l, g_w4l);
    cudaGetSymbolAddress((void**)&wfh, g_wfh);  cudaGetSymbolAddress((void**)&wfl, g_wfl);
    cudaGetSymbolAddress((void**)&wihT, g_wihT);
    cudaGetSymbolAddress((void**)&whhT, g_whhT);
    cudaGetSymbolAddress((void**)&pwT, g_pwT);
    cudaGetSymbolAddress((void**)&qwT, g_qwT);

    auto c1 = mmagemm_kernel<3, 64, 32, 64, 32, true, true, 1024>;
    auto c2 = mmagemm_kernel<32, 32, 64, 512, 64, true, true, 256>;
    auto c3 = mmagemm_kernel<64, 16, 128, 1024, 128, true, true, 64>;
    auto c4 = mmagemm_kernel<128, 8, 256, 2048, 128, true, true, 16>;
    auto fc = mmagemm_kernel<1, 2, 256, 4096, 32, false, false, 1>;   // NT=32 -> 128 CTAs
    const int smA  = 128 * 40 * 2 * 2;                 // 20480
    const int sm1 = smA + 2 * 32 * 40 * 2 * 2;         // 30720
    const int sm2 = smA + 2 * 64 * 40 * 2 * 2;         // 40960
    const int sm3 = smA + 2 * 128 * 40 * 2 * 2;        // 61440
    cudaFuncSetAttribute(c1, cudaFuncAttributeMaxDynamicSharedMemorySize, sm1);
    cudaFuncSetAttribute(c2, cudaFuncAttributeMaxDynamicSharedMemorySize, sm2);
    cudaFuncSetAttribute(c3, cudaFuncAttributeMaxDynamicSharedMemorySize, sm3);
    cudaFuncSetAttribute(c4, cudaFuncAttributeMaxDynamicSharedMemorySize, sm3);
    cudaFuncSetAttribute(fc, cudaFuncAttributeMaxDynamicSharedMemorySize, sm1);

    PackArgs pa;
    pa.w1 = c1_w; pa.w2 = c2_w; pa.w3 = c3_w; pa.w4 = c4_w; pa.wf = fc_w;
    pa.wih = gru_wih; pa.whh = gru_whh; pa.pw = prior_w; pa.qw = post_w;
    pa.w1h = w1h; pa.w1l = w1l; pa.w2h = w2h; pa.w2l = w2l;
    pa.w3h = w3h; pa.w3l = w3l; pa.w4h = w4h; pa.w4l = w4l;
    pa.wfh = wfh; pa.wfl = wfl;
    pa.wihT = wihT; pa.whhT = whhT; pa.pwT = pwT; pa.qwT = qwT;

    // 0: all weight packing / transposes in one launch
    pack_all_kernel<<<1024, 256>>>(pa);
    // 1: conv1 GEMM (M=2097152, N=32, K=64)
    c1<<<dim3(16384, 1), 256, sm1>>>(states, w1h, w1l, c1_b, b1);
    // 2: conv2 GEMM (M=524288, N=64, K=512)
    c2<<<dim3(4096, 1), 256, sm2>>>(b1, w2h, w2l, c2_b, b2);
    // 3 <- profiled: conv3 GEMM (M=131072, N=128, K=1024)
    c3<<<dim3(1024, 1), 256, sm3>>>(b2, w3h, w3l, c3_b, b3);
    // 4: conv4 GEMM (M=32768, N=256, K=2048)
    c4<<<dim3(256, 2), 256, sm3>>>(b3, w4h, w4l, c4_b, b4);
    // 5: fc GEMM (M=2048, N=256, K=4096) — NT=32, grid (16,8) = 128 CTAs
    fc<<<dim3(16, 8), 256, sm1>>>(b4, wfh, wfl, fc_b, feats);
    // 6: scan (coalesced transposed weights)
    scan_kernel<<<BB, 384>>>(actions, feats, wihT, whhT, gru_bih, gru_bhh,
                             pwT, prior_b, qwT, post_b, eps, out);
}

// round 16
// speedup vs baseline: 1.9352x; 1.0290x over previous
#include <cuda_runtime.h>
#include <cuda_bf16.h>
#include <cstdint>

#define BB 32
#define TT 64
#define NFR 2048
#define AA 6
#define LL 32
#define HH 128
#define FD 256

// ---------------- static device scratch ----------------
__device__ float g_b1[(size_t)NFR * 32 * 32 * 32];
__device__ float g_b2[(size_t)NFR * 64 * 16 * 16];
__device__ float g_b3[(size_t)NFR * 128 * 8 * 8];
__device__ float g_b4[(size_t)NFR * 256 * 16];
__device__ float g_feats[(size_t)NFR * FD];
// bf16 hi/lo weight images, [oc][Kpad] row-major
__device__ __align__(16) __nv_bfloat16 g_w2h[64 * 512],   g_w2l[64 * 512];
__device__ __align__(16) __nv_bfloat16 g_w3h[128 * 1024], g_w3l[128 * 1024];
__device__ __align__(16) __nv_bfloat16 g_w4h[256 * 2048], g_w4l[256 * 2048];
__device__ __align__(16) __nv_bfloat16 g_wfh[256 * 4096], g_wfl[256 * 4096];
// transposed scan weights: [k][j]
__device__ __align__(16) float g_wihT[38 * 384];
__device__ __align__(16) float g_whhT[128 * 384];
__device__ __align__(16) float g_pwT[128 * 64];
__device__ __align__(16) float g_qwT[384 * 64];

// ---------------- helpers ----------------
__device__ __forceinline__ uint32_t smem_u32(const void* p) {
    uint32_t a;
    asm("{ .reg .u64 t; cvta.to.shared.u64 t, %1; cvt.u32.u64 %0, t; }" : "=r"(a) : "l"(p));
    return a;
}
__device__ __forceinline__ void bsplit(float v, __nv_bfloat16& h, __nv_bfloat16& l) {
    h = __float2bfloat16(v);
    l = __float2bfloat16(v - __bfloat162float(h));
}
__device__ __forceinline__ void pack2(float v0, float v1, uint32_t& hw, uint32_t& lw) {
    __nv_bfloat16 h0, l0, h1, l1;
    bsplit(v0, h0, l0);
    bsplit(v1, h1, l1);
    hw = (uint32_t)__bfloat16_as_ushort(h0) | ((uint32_t)__bfloat16_as_ushort(h1) << 16);
    lw = (uint32_t)__bfloat16_as_ushort(l0) | ((uint32_t)__bfloat16_as_ushort(l1) << 16);
}
__device__ __forceinline__ void ldmx4(uint32_t* r, uint32_t addr) {
    asm volatile("ldmatrix.sync.aligned.m8n8.x4.shared.b16 {%0,%1,%2,%3}, [%4];"
                 : "=r"(r[0]), "=r"(r[1]), "=r"(r[2]), "=r"(r[3]) : "r"(addr));
}
__device__ __forceinline__ void mma16816(float* c, const uint32_t* a, const uint32_t* b) {
    asm volatile(
        "mma.sync.aligned.m16n8k16.row.col.f32.bf16.bf16.f32 "
        "{%0,%1,%2,%3}, {%4,%5,%6,%7}, {%8,%9}, {%0,%1,%2,%3};"
        : "+f"(c[0]), "+f"(c[1]), "+f"(c[2]), "+f"(c[3])
        : "r"(a[0]), "r"(a[1]), "r"(a[2]), "r"(a[3]), "r"(b[0]), "r"(b[1]));
}
__device__ __forceinline__ void cpasync16(uint32_t dst, const void* src) {
    asm volatile("cp.async.ca.shared.global [%0], [%1], 16;" :: "r"(dst), "l"(src));
}
#define CP_COMMIT() asm volatile("cp.async.commit_group;" ::: "memory")
#define CP_WAIT0()  asm volatile("cp.async.wait_group 0;" ::: "memory")

// ---------------- conv1 + fused weight packing (tail blocks) ----------------
// Blocks < NB1 run conv1 as im2col GEMM with INLINE B split (K=64 tiny -> safe).
// Blocks >= NB1 grid-stride pack w2/w3/w4/wf (bf16 hi/lo) + scan transposes.
struct PackArgs {
    const float *w2, *w3, *w4, *wf, *wih, *whh, *pw, *qw;
    __nv_bfloat16 *w2h, *w2l, *w3h, *w3l, *w4h, *w4l, *wfh, *wfl;
    float *wihT, *whhT, *pwT, *qwT;
};
__device__ __forceinline__ void pack_one(const float* w, __nv_bfloat16* bh,
                                         __nv_bfloat16* bl, int idx, int Kr) {
    float v = w[idx];
    __nv_bfloat16 h, l;
    bsplit(v, h, l);
    bh[idx] = h;
    bl[idx] = l;
    (void)Kr;
}
__global__ void __launch_bounds__(256)
conv1_pack_kernel(const float* __restrict__ in, const float* __restrict__ gW,
                  const float* __restrict__ bias, float* __restrict__ outp,
                  PackArgs pa, int NB1) {
    constexpr int AS = 40, IH = 64, OW = 32, NT = 32, KR = 48, POS = 1024;
    constexpr int WN = NT / 2, NTI = WN / 8, NPAIR = WN / 16;

    if ((int)blockIdx.x >= NB1) {
        // ---- packing tail ----
        constexpr int S2 = 64 * 512,     C2 = S2;
        constexpr int S3 = 128 * 1024,   C3 = C2 + S3;
        constexpr int S4 = 256 * 2048,   C4 = C3 + S4;
        constexpr int S5 = 256 * 4096,   C5 = C4 + S5;
        constexpr int S6 = 38 * 384,     C6 = C5 + S6;
        constexpr int S7 = 128 * 384,    C7 = C6 + S7;
        constexpr int S8 = 128 * 64,     C8 = C7 + S8;
        constexpr int S9 = 384 * 64,     C9 = C8 + S9;
        int nb = gridDim.x - NB1;
        for (int idx = ((int)blockIdx.x - NB1) * 256 + threadIdx.x; idx < C9;
             idx += nb * 256) {
            if (idx < C2)      pack_one(pa.w2, pa.w2h, pa.w2l, idx, 512);
            else if (idx < C3) pack_one(pa.w3, pa.w3h, pa.w3l, idx - C2, 1024);
            else if (idx < C4) pack_one(pa.w4, pa.w4h, pa.w4l, idx - C3, 2048);
            else if (idx < C5) pack_one(pa.wf, pa.wfh, pa.wfl, idx - C4, 4096);
            else if (idx < C6) { int t = idx - C5; int k = t / 384, j = t % 384;
                                 pa.wihT[t] = pa.wih[(size_t)j * 38 + k]; }
            else if (idx < C7) { int t = idx - C6; int k = t / 384, j = t % 384;
                                 pa.whhT[t] = pa.whh[(size_t)j * 128 + k]; }
            else if (idx < C8) { int t = idx - C7; int k = t / 64, j = t % 64;
                                 pa.pwT[t] = pa.pw[(size_t)j * 128 + k]; }
            else               { int t = idx - C8; int k = t / 64, j = t % 64;
                                 pa.qwT[t] = pa.qw[(size_t)j * 384 + k]; }
        }
        return;
    }

    // ---- conv1 GEMM (inline B split, NCH=2) ----
    extern __shared__ __align__(16) char smem[];
    __nv_bfloat16* Ah = (__nv_bfloat16*)smem;
    __nv_bfloat16* Al = Ah + 128 * AS;
    __nv_bfloat16* Bh = Al + 128 * AS;
    __nv_bfloat16* Bl = Bh + NT * AS;

    const uint32_t sb   = smem_u32(smem);
    const uint32_t ah_b = sb;
    const uint32_t al_b = sb + 128 * AS * 2;
    const uint32_t bh_b = sb + 128 * AS * 4;
    const uint32_t bl_b = bh_b + NT * AS * 2;

    const int tid = threadIdx.x, lane = tid & 31, wid = tid >> 5;
    const int wm = wid & 3, wn = wid >> 2;
    const int m0 = blockIdx.x * 128;

    float acc[2][NTI][4];
#pragma unroll
    for (int mt = 0; mt < 2; ++mt)
#pragma unroll
        for (int nt = 0; nt < NTI; ++nt)
#pragma unroll
            for (int q = 0; q < 4; ++q) acc[mt][nt][q] = 0.f;

    const int r  = tid & 127;
    const int kg = tid >> 7;
    const int m  = m0 + r;
    const int fr = m / POS;
    const int pg = m & (POS - 1);
    const int oy = pg / OW, ox = pg & (OW - 1);
    const int iyb = 2 * oy - 1, ixb = 2 * ox - 1;
    const int boc = tid >> 4;            // 0..15
    const int bk2 = (tid & 15) * 2;

    float va[16];
    float wb[4];

    auto GATHER = [&](int ch) {
        const int ic = ch * 2 + kg;
        const bool icok = (ic < 3);
        const float* plane = in + ((size_t)fr * 3 + (icok ? ic : 0)) * IH * IH;
#pragma unroll
        for (int ky = 0; ky < 4; ++ky) {
            int iy = iyb + ky;
            bool yok = icok && iy >= 0 && iy < IH;
            const float* rp = plane + iy * IH;
            va[4 * ky + 0] = (yok && ixb >= 0)     ? rp[ixb]     : 0.f;
            va[4 * ky + 1] = yok                   ? rp[ixb + 1] : 0.f;
            va[4 * ky + 2] = yok                   ? rp[ixb + 2] : 0.f;
            va[4 * ky + 3] = (yok && ixb + 3 < IH) ? rp[ixb + 3] : 0.f;
        }
    };
    auto LDGB = [&](int ch) {
        const int k = ch * 32 + bk2;
#pragma unroll
        for (int g = 0; g < 2; ++g) {
            int oc = boc + 16 * g;
            float2 v = make_float2(0.f, 0.f);
            if (k < KR) v = *(const float2*)&gW[(size_t)oc * KR + k];
            wb[2 * g] = v.x; wb[2 * g + 1] = v.y;
        }
    };
    auto STOREA = [&]() {
        uint32_t hw[8], lw[8];
#pragma unroll
        for (int q = 0; q < 8; ++q) pack2(va[2 * q], va[2 * q + 1], hw[q], lw[q]);
        uint32_t dof = r * AS + kg * 16;
        *(uint4*)&Ah[dof]     = *(uint4*)&hw[0];
        *(uint4*)&Ah[dof + 8] = *(uint4*)&hw[4];
        *(uint4*)&Al[dof]     = *(uint4*)&lw[0];
        *(uint4*)&Al[dof + 8] = *(uint4*)&lw[4];
    };
    auto STSB = [&]() {
#pragma unroll
        for (int g = 0; g < 2; ++g) {
            int oc = boc + 16 * g;
            uint32_t hw_, lw_;
            pack2(wb[2 * g], wb[2 * g + 1], hw_, lw_);
            ((uint32_t*)Bh)[oc * 20 + (bk2 >> 1)] = hw_;
            ((uint32_t*)Bl)[oc * 20 + (bk2 >> 1)] = lw_;
        }
    };

    GATHER(0); LDGB(0);
    STOREA(); STSB();
    GATHER(1); LDGB(1);
    __syncthreads();

    for (int ch = 0; ch < 2; ++ch) {
#pragma unroll
        for (int ks = 0; ks < 32; ks += 16) {
            uint32_t ahf[2][4], alf[2][4];
#pragma unroll
            for (int mt = 0; mt < 2; ++mt) {
                int row = wm * 32 + mt * 16 + (lane & 15);
                int koff = ks + ((lane >> 4) << 3);
                uint32_t off = (uint32_t)(row * AS + koff) * 2;
                ldmx4(ahf[mt], ah_b + off);
                ldmx4(alf[mt], al_b + off);
            }
#pragma unroll
            for (int np = 0; np < NPAIR; ++np) {
                uint32_t bhf[4], blf[4];
                int n = wn * WN + np * 16 + (lane & 7) + ((lane >> 4) << 3);
                int koff = ks + (((lane >> 3) & 1) << 3);
                uint32_t off = (uint32_t)(n * AS + koff) * 2;
                ldmx4(bhf, bh_b + off);
                ldmx4(blf, bl_b + off);
#pragma unroll
                for (int s = 0; s < 2; ++s) {
                    int nt = np * 2 + s;
#pragma unroll
                    for (int mt = 0; mt < 2; ++mt) {
                        mma16816(acc[mt][nt], ahf[mt], bhf + 2 * s);
                        mma16816(acc[mt][nt], ahf[mt], blf + 2 * s);
                        mma16816(acc[mt][nt], alf[mt], bhf + 2 * s);
                    }
                }
            }
        }
        __syncthreads();
        if (ch == 0) { STOREA(); STSB(); __syncthreads(); }
    }

#pragma unroll
    for (int mt = 0; mt < 2; ++mt) {
#pragma unroll
        for (int nt = 0; nt < NTI; ++nt) {
            int oc = wn * WN + nt * 8 + 2 * (lane & 3);
            float b0 = bias[oc], b1 = bias[oc + 1];
#pragma unroll
            for (int half = 0; half < 2; ++half) {
                int mm = m0 + wm * 32 + mt * 16 + (lane >> 2) + half * 8;
                int frr = mm / POS;
                int pgg = mm & (POS - 1);
                size_t base = ((size_t)frr * 32 + oc) * POS + pgg;
                outp[base]       = fmaxf(acc[mt][nt][2 * half]     + b0, 0.f);
                outp[base + POS] = fmaxf(acc[mt][nt][2 * half + 1] + b1, 0.f);
            }
        }
    }
}

// ---------------- pipelined tensor-core im2col GEMM (prepacked B, R13/R15 config) ----
template <int ICR, int IH, int OC, int KTOT, int NT, bool IM2COL, bool RELU, int POS>
__global__ void __launch_bounds__(256)
mmagemm_kernel(const float* __restrict__ in, const __nv_bfloat16* __restrict__ gBh,
               const __nv_bfloat16* __restrict__ gBl, const float* __restrict__ bias,
               float* __restrict__ outp) {
    constexpr int AS  = 40;
    constexpr int OW  = IH / 2;
    constexpr int WN  = NT / 2;
    constexpr int NTI = WN / 8;
    constexpr int NPAIR = WN / 16;
    constexpr int NCH = KTOT / 32;
    constexpr uint32_t BBUF = NT * AS * 2 * 2;

    extern __shared__ __align__(16) char smem[];
    __nv_bfloat16* Ah = (__nv_bfloat16*)smem;
    __nv_bfloat16* Al = Ah + 128 * AS;

    const uint32_t sb   = smem_u32(smem);
    const uint32_t ah_b = sb;
    const uint32_t al_b = sb + 128 * AS * 2;
    const uint32_t bbase = sb + 128 * AS * 4;

    const int tid = threadIdx.x, lane = tid & 31, wid = tid >> 5;
    const int wm = wid & 3, wn = wid >> 2;
    const int m0 = blockIdx.x * 128;
    const int n0g = blockIdx.y * NT;

    float acc[2][NTI][4];
#pragma unroll
    for (int mt = 0; mt < 2; ++mt)
#pragma unroll
        for (int nt = 0; nt < NTI; ++nt)
#pragma unroll
            for (int q = 0; q < 4; ++q) acc[mt][nt][q] = 0.f;

    const int r  = tid & 127;
    const int kg = tid >> 7;
    const int m  = m0 + r;
    const int fr = m / POS;
    const int pg = m & (POS - 1);
    const int oy = pg / OW, ox = pg & (OW - 1);
    const int iyb = 2 * oy - 1, ixb = 2 * ox - 1;

    float va[16];

    auto GATHER = [&](int ch) {
        if (IM2COL) {
            const int ic = ch * 2 + kg;
            const bool icok = (ic < ICR);
            const float* plane = in + ((size_t)fr * ICR + (icok ? ic : 0)) * IH * IH;
#pragma unroll
            for (int ky = 0; ky < 4; ++ky) {
                int iy = iyb + ky;
                bool yok = icok && iy >= 0 && iy < IH;
                const float* rp = plane + iy * IH;
                va[4 * ky + 0] = (yok && ixb >= 0)     ? rp[ixb]     : 0.f;
                va[4 * ky + 1] = yok                   ? rp[ixb + 1] : 0.f;
                va[4 * ky + 2] = yok                   ? rp[ixb + 2] : 0.f;
                va[4 * ky + 3] = (yok && ixb + 3 < IH) ? rp[ixb + 3] : 0.f;
            }
        } else {
            const float* rp = in + (size_t)m * KTOT + ch * 32 + kg * 16;
#pragma unroll
            for (int q = 0; q < 4; ++q) {
                float4 v = *(const float4*)(rp + q * 4);
                va[4 * q + 0] = v.x; va[4 * q + 1] = v.y;
                va[4 * q + 2] = v.z; va[4 * q + 3] = v.w;
            }
        }
    };
    auto STOREA = [&]() {
        uint32_t hw[8], lw[8];
#pragma unroll
        for (int q = 0; q < 8; ++q) pack2(va[2 * q], va[2 * q + 1], hw[q], lw[q]);
        uint32_t dof = r * AS + kg * 16;
        *(uint4*)&Ah[dof]     = *(uint4*)&hw[0];
        *(uint4*)&Ah[dof + 8] = *(uint4*)&hw[4];
        *(uint4*)&Al[dof]     = *(uint4*)&lw[0];
        *(uint4*)&Al[dof + 8] = *(uint4*)&lw[4];
    };
    auto STAGEB = [&](int ch) {
        uint32_t bd = bbase + (ch & 1) * BBUF;
        for (int i = tid; i < NT * 4; i += 256) {
            int n = i >> 2, q = i & 3;
            size_t go = (size_t)(n0g + n) * KTOT + ch * 32 + q * 8;
            cpasync16(bd + n * 80 + q * 16, gBh + go);
            cpasync16(bd + NT * 80 + n * 80 + q * 16, gBl + go);
        }
    };

    GATHER(0);
    STAGEB(0);
    CP_COMMIT();
    STOREA();
    if (NCH > 1) GATHER(1);
    CP_WAIT0();
    __syncthreads();

    for (int ch = 0; ch < NCH; ++ch) {
        if (ch + 1 < NCH) STAGEB(ch + 1);
        CP_COMMIT();

        const uint32_t bh_b = bbase + (ch & 1) * BBUF;
        const uint32_t bl_b = bh_b + NT * 80;
#pragma unroll
        for (int ks = 0; ks < 32; ks += 16) {
            uint32_t ahf[2][4], alf[2][4];
#pragma unroll
            for (int mt = 0; mt < 2; ++mt) {
                int row = wm * 32 + mt * 16 + (lane & 15);
                int koff = ks + ((lane >> 4) << 3);
                uint32_t off = (uint32_t)(row * AS + koff) * 2;
                ldmx4(ahf[mt], ah_b + off);
                ldmx4(alf[mt], al_b + off);
            }
#pragma unroll
            for (int np = 0; np < NPAIR; ++np) {
                uint32_t bhf[4], blf[4];
                int n = wn * WN + np * 16 + (lane & 7) + ((lane >> 4) << 3);
                int koff = ks + (((lane >> 3) & 1) << 3);
                uint32_t off = (uint32_t)(n * AS + koff) * 2;
                ldmx4(bhf, bh_b + off);
                ldmx4(blf, bl_b + off);
#pragma unroll
                for (int s = 0; s < 2; ++s) {
                    int nt = np * 2 + s;
#pragma unroll
                    for (int mt = 0; mt < 2; ++mt) {
                        mma16816(acc[mt][nt], ahf[mt], bhf + 2 * s);
                        mma16816(acc[mt][nt], ahf[mt], blf + 2 * s);
                        mma16816(acc[mt][nt], alf[mt], bhf + 2 * s);
                    }
                }
            }
        }
        __syncthreads();
        if (ch + 1 < NCH) {
            STOREA();
            if (ch + 2 < NCH) GATHER(ch + 2);
            CP_WAIT0();
            __syncthreads();
        }
    }

#pragma unroll
    for (int mt = 0; mt < 2; ++mt) {
#pragma unroll
        for (int nt = 0; nt < NTI; ++nt) {
            int oc = n0g + wn * WN + nt * 8 + 2 * (lane & 3);
            float b0 = bias[oc], b1 = bias[oc + 1];
#pragma unroll
            for (int half = 0; half < 2; ++half) {
                int mm = m0 + wm * 32 + mt * 16 + (lane >> 2) + half * 8;
                float x0 = acc[mt][nt][2 * half]     + b0;
                float x1 = acc[mt][nt][2 * half + 1] + b1;
                if (RELU) { x0 = fmaxf(x0, 0.f); x1 = fmaxf(x1, 0.f); }
                if (IM2COL) {
                    int frr = mm / POS;
                    int pgg = mm & (POS - 1);
                    size_t base = ((size_t)frr * OC + oc) * POS + pgg;
                    outp[base]       = x0;
                    outp[base + POS] = x1;
                } else {
                    *(float2*)&outp[(size_t)mm * OC + oc] = make_float2(x0, x1);
                }
            }
        }
    }
}

// ---------------- sequential scan (coalesced transposed weights) ----------------
__global__ void scan_kernel(const float* __restrict__ actions, const float* __restrict__ feats,
                            const float* __restrict__ wihT, const float* __restrict__ whhT,
                            const float* __restrict__ bih, const float* __restrict__ bhh,
                            const float* __restrict__ pwT, const float* __restrict__ pb,
                            const float* __restrict__ qwT, const float* __restrict__ qb,
                            const float* __restrict__ eps, float* __restrict__ out) {
    int b = blockIdx.x, tid = threadIdx.x;
    __shared__ float x_s[40];
    __shared__ __align__(16) float h_s[HH];
    __shared__ __align__(16) float f_s[FD];
    __shared__ float gi_s[3 * HH], gh_s[3 * HH];
    __shared__ float p_s[2 * LL], q_s[2 * LL];

    if (tid < LL + AA) x_s[tid] = 0.f;
    if (tid < HH) h_s[tid] = 0.f;

    const float bih_j = bih[tid];
    const float bhh_j = bhh[tid];

    float* out_mup = out;
    float* out_lvp = out + (size_t)NFR * LL;
    float* out_muq = out + (size_t)NFR * LL * 2;
    float* out_lvq = out + (size_t)NFR * LL * 3;
    float* out_h   = out + (size_t)NFR * LL * 4;
    float* out_z   = out + (size_t)NFR * LL * 4 + (size_t)NFR * HH;

    for (int t = 0; t < TT; ++t) {
        int bt = b * TT + t;
        if (tid >= LL && tid < LL + AA) x_s[tid] = actions[(size_t)bt * AA + (tid - LL)];
        if (tid < FD) f_s[tid] = feats[(size_t)bt * FD + tid];
        __syncthreads();

        {
            const int j = tid;
            float a0 = 0.f, a1 = 0.f;
#pragma unroll
            for (int k = 0; k < 38; k += 2) {
                a0 = fmaf(x_s[k],     wihT[(size_t)k * 384 + j],       a0);
                a1 = fmaf(x_s[k + 1], wihT[(size_t)(k + 1) * 384 + j], a1);
            }
            float g0 = 0.f, g1 = 0.f, g2 = 0.f, g3 = 0.f;
#pragma unroll
            for (int k = 0; k < HH; k += 4) {
                g0 = fmaf(h_s[k],     whhT[(size_t)k * 384 + j],       g0);
                g1 = fmaf(h_s[k + 1], whhT[(size_t)(k + 1) * 384 + j], g1);
                g2 = fmaf(h_s[k + 2], whhT[(size_t)(k + 2) * 384 + j], g2);
                g3 = fmaf(h_s[k + 3], whhT[(size_t)(k + 3) * 384 + j], g3);
            }
            gi_s[j] = bih_j + a0 + a1;
            gh_s[j] = bhh_j + (g0 + g1) + (g2 + g3);
        }
        __syncthreads();

        if (tid < HH) {
            int u = tid;
            float r  = 1.f / (1.f + expf(-(gi_s[u] + gh_s[u])));
            float zz = 1.f / (1.f + expf(-(gi_s[u + HH] + gh_s[u + HH])));
            float nn = tanhf(gi_s[u + 2 * HH] + r * gh_s[u + 2 * HH]);
            h_s[u] = (1.f - zz) * nn + zz * h_s[u];
        }
        __syncthreads();

        if (tid < 2 * LL) {
            const int j = tid;
            float g0 = 0.f, g1 = 0.f, g2 = 0.f, g3 = 0.f;
#pragma unroll
            for (int k = 0; k < HH; k += 4) {
                g0 = fmaf(h_s[k],     pwT[(size_t)k * 64 + j],       g0);
                g1 = fmaf(h_s[k + 1], pwT[(size_t)(k + 1) * 64 + j], g1);
                g2 = fmaf(h_s[k + 2], pwT[(size_t)(k + 2) * 64 + j], g2);
                g3 = fmaf(h_s[k + 3], pwT[(size_t)(k + 3) * 64 + j], g3);
            }
            p_s[j] = pb[j] + (g0 + g1) + (g2 + g3);
        } else if (tid < 4 * LL) {
            const int j = tid - 2 * LL;
            float g0 = 0.f, g1 = 0.f, g2 = 0.f, g3 = 0.f;
#pragma unroll
            for (int k = 0; k < HH; k += 4) {
                g0 = fmaf(h_s[k],     qwT[(size_t)k * 64 + j],       g0);
                g1 = fmaf(h_s[k + 1], qwT[(size_t)(k + 1) * 64 + j], g1);
                g2 = fmaf(h_s[k + 2], qwT[(size_t)(k + 2) * 64 + j], g2);
                g3 = fmaf(h_s[k + 3], qwT[(size_t)(k + 3) * 64 + j], g3);
            }
#pragma unroll
            for (int k = 0; k < FD; k += 4) {
                g0 = fmaf(f_s[k],     qwT[(size_t)(HH + k) * 64 + j],     g0);
                g1 = fmaf(f_s[k + 1], qwT[(size_t)(HH + k + 1) * 64 + j], g1);
                g2 = fmaf(f_s[k + 2], qwT[(size_t)(HH + k + 2) * 64 + j], g2);
                g3 = fmaf(f_s[k + 3], qwT[(size_t)(HH + k + 3) * 64 + j], g3);
            }
            q_s[j] = qb[j] + (g0 + g1) + (g2 + g3);
        }
        __syncthreads();

        if (tid < HH) out_h[(size_t)bt * HH + tid] = h_s[tid];
        if (tid < LL) {
            int l = tid;
            out_mup[(size_t)bt * LL + l] = p_s[l];
            out_lvp[(size_t)bt * LL + l] = p_s[l + LL];
            float muq = q_s[l], lvq = q_s[l + LL];
            out_muq[(size_t)bt * LL + l] = muq;
            out_lvq[(size_t)bt * LL + l] = lvq;
            float z = muq + expf(0.5f * lvq) * eps[(size_t)bt * LL + l];
            out_z[(size_t)bt * LL + l] = z;
            x_s[l] = z;
        }
        __syncthreads();
    }
}

// ---------------- launch ----------------
extern "C" void kernel_launch(void* const* d_in, const int* in_sizes, int n_in,
                              void* d_out, int out_size) {
    const float* states  = (const float*)d_in[0];
    const float* actions = (const float*)d_in[1];
    const float* c1_w = (const float*)d_in[2];
    const float* c1_b = (const float*)d_in[3];
    const float* c2_w = (const float*)d_in[4];
    const float* c2_b = (const float*)d_in[5];
    const float* c3_w = (const float*)d_in[6];
    const float* c3_b = (const float*)d_in[7];
    const float* c4_w = (const float*)d_in[8];
    const float* c4_b = (const float*)d_in[9];
    const float* fc_w = (const float*)d_in[10];
    const float* fc_b = (const float*)d_in[11];
    const float* gru_wih = (const float*)d_in[12];
    const float* gru_whh = (const float*)d_in[13];
    const float* gru_bih = (const float*)d_in[14];
    const float* gru_bhh = (const float*)d_in[15];
    const float* prior_w = (const float*)d_in[16];
    const float* prior_b = (const float*)d_in[17];
    const float* post_w  = (const float*)d_in[18];
    const float* post_b  = (const float*)d_in[19];
    const float* eps     = (const float*)d_in[20];
    float* out = (float*)d_out;

    float *b1, *b2, *b3, *b4, *feats, *wihT, *whhT, *pwT, *qwT;
    __nv_bfloat16 *w2h, *w2l, *w3h, *w3l, *w4h, *w4l, *wfh, *wfl;
    cudaGetSymbolAddress((void**)&b1, g_b1);
    cudaGetSymbolAddress((void**)&b2, g_b2);
    cudaGetSymbolAddress((void**)&b3, g_b3);
    cudaGetSymbolAddress((void**)&b4, g_b4);
    cudaGetSymbolAddress((void**)&feats, g_feats);
    cudaGetSymbolAddress((void**)&w2h, g_w2h);  cudaGetSymbolAddress((void**)&w2l, g_w2l);
    cudaGetSymbolAddress((void**)&w3h, g_w3h);  cudaGetSymbolAddress((void**)&w3l, g_w3l);
    cudaGetSymbolAddress((void**)&w4h, g_w4h);  cudaGetSymbolAddress((void**)&w4l, g_w4l);
    cudaGetSymbolAddress((void**)&wfh, g_wfh);  cudaGetSymbolAddress((void**)&wfl, g_wfl);
    cudaGetSymbolAddress((void**)&wihT, g_wihT);
    cudaGetSymbolAddress((void**)&whhT, g_whhT);
    cudaGetSymbolAddress((void**)&pwT, g_pwT);
    cudaGetSymbolAddress((void**)&qwT, g_qwT);

    auto c2 = mmagemm_kernel<32, 32, 64, 512, 64, true, true, 256>;
    auto c3 = mmagemm_kernel<64, 16, 128, 1024, 128, true, true, 64>;
    auto c4 = mmagemm_kernel<128, 8, 256, 2048, 128, true, true, 16>;
    auto fc = mmagemm_kernel<1, 2, 256, 4096, 32, false, false, 1>;
    const int smA  = 128 * 40 * 2 * 2;                 // 20480
    const int sm1 = smA + 32 * 40 * 2 * 2;             // 25600 (conv1: single-buf inline B)
    const int sm2 = smA + 2 * 64 * 40 * 2 * 2;         // 40960
    const int sm3 = smA + 2 * 128 * 40 * 2 * 2;        // 61440
    const int smf = smA + 2 * 32 * 40 * 2 * 2;         // 30720
    cudaFuncSetAttribute(conv1_pack_kernel, cudaFuncAttributeMaxDynamicSharedMemorySize, sm1);
    cudaFuncSetAttribute(c2, cudaFuncAttributeMaxDynamicSharedMemorySize, sm2);
    cudaFuncSetAttribute(c3, cudaFuncAttributeMaxDynamicSharedMemorySize, sm3);
    cudaFuncSetAttribute(c4, cudaFuncAttributeMaxDynamicSharedMemorySize, sm3);
    cudaFuncSetAttribute(fc, cudaFuncAttributeMaxDynamicSharedMemorySize, smf);

    PackArgs pa;
    pa.w2 = c2_w; pa.w3 = c3_w; pa.w4 = c4_w; pa.wf = fc_w;
    pa.wih = gru_wih; pa.whh = gru_whh; pa.pw = prior_w; pa.qw = post_w;
    pa.w2h = w2h; pa.w2l = w2l; pa.w3h = w3h; pa.w3l = w3l;
    pa.w4h = w4h; pa.w4l = w4l; pa.wfh = wfh; pa.wfl = wfl;
    pa.wihT = wihT; pa.whhT = whhT; pa.pwT = pwT; pa.qwT = qwT;

    // 0: conv1 GEMM (inline B) + weight packing tail blocks
    conv1_pack_kernel<<<16384 + 1024, 256, sm1>>>(states, c1_w, c1_b, b1, pa, 16384);
    // 1: conv2 GEMM (M=524288, N=64, K=512)
    c2<<<dim3(4096, 1), 256, sm2>>>(b1, w2h, w2l, c2_b, b2);
    // 2: conv3 GEMM (M=131072, N=128, K=1024)
    c3<<<dim3(1024, 1), 256, sm3>>>(b2, w3h, w3l, c3_b, b3);
    // 3 <- profiled: conv4 GEMM (M=32768, N=256, K=2048)
    c4<<<dim3(256, 2), 256, sm3>>>(b3, w4h, w4l, c4_b, b4);
    // 4: fc GEMM (M=2048, N=256, K=4096) — NT=32, grid (16,8)
    fc<<<dim3(16, 8), 256, smf>>>(b4, wfh, wfl, fc_b, feats);
    // 5: scan
    scan_kernel<<<BB, 384>>>(actions, feats, wihT, whhT, gru_bih, gru_bhh,
                             pwT, prior_b, qwT, post_b, eps, out);
}

// round 17
// speedup vs baseline: 2.0637x; 1.0664x over previous
#include <cuda_runtime.h>
#include <cuda_bf16.h>
#include <cstdint>

#define BB 32
#define TT 64
#define NFR 2048
#define AA 6
#define LL 32
#define HH 128
#define FD 256

// ---------------- static device scratch ----------------
__device__ float g_b1[(size_t)NFR * 32 * 32 * 32];
__device__ float g_b2[(size_t)NFR * 64 * 16 * 16];
__device__ float g_b3[(size_t)NFR * 128 * 8 * 8];
__device__ float g_b4[(size_t)NFR * 256 * 16];
__device__ float g_feats[(size_t)NFR * FD];
// bf16 hi/lo weight images, [oc][Kpad] row-major
__device__ __align__(16) __nv_bfloat16 g_w2h[64 * 512],   g_w2l[64 * 512];
__device__ __align__(16) __nv_bfloat16 g_w3h[128 * 1024], g_w3l[128 * 1024];
__device__ __align__(16) __nv_bfloat16 g_w4h[256 * 2048], g_w4l[256 * 2048];
__device__ __align__(16) __nv_bfloat16 g_wfh[256 * 4096], g_wfl[256 * 4096];
// float4-packed transposed scan weights: element (k4, j, q) at [(k4*J + j)*4 + q]
__device__ __align__(16) float g_wihT[40 * 384];    // k padded 38->40
__device__ __align__(16) float g_whhT[128 * 384];
__device__ __align__(16) float g_pwT[128 * 64];
__device__ __align__(16) float g_qwT[384 * 64];

// ---------------- helpers ----------------
__device__ __forceinline__ uint32_t smem_u32(const void* p) {
    uint32_t a;
    asm("{ .reg .u64 t; cvta.to.shared.u64 t, %1; cvt.u32.u64 %0, t; }" : "=r"(a) : "l"(p));
    return a;
}
__device__ __forceinline__ void bsplit(float v, __nv_bfloat16& h, __nv_bfloat16& l) {
    h = __float2bfloat16(v);
    l = __float2bfloat16(v - __bfloat162float(h));
}
__device__ __forceinline__ void pack2(float v0, float v1, uint32_t& hw, uint32_t& lw) {
    __nv_bfloat16 h0, l0, h1, l1;
    bsplit(v0, h0, l0);
    bsplit(v1, h1, l1);
    hw = (uint32_t)__bfloat16_as_ushort(h0) | ((uint32_t)__bfloat16_as_ushort(h1) << 16);
    lw = (uint32_t)__bfloat16_as_ushort(l0) | ((uint32_t)__bfloat16_as_ushort(l1) << 16);
}
__device__ __forceinline__ void ldmx4(uint32_t* r, uint32_t addr) {
    asm volatile("ldmatrix.sync.aligned.m8n8.x4.shared.b16 {%0,%1,%2,%3}, [%4];"
                 : "=r"(r[0]), "=r"(r[1]), "=r"(r[2]), "=r"(r[3]) : "r"(addr));
}
__device__ __forceinline__ void mma16816(float* c, const uint32_t* a, const uint32_t* b) {
    asm volatile(
        "mma.sync.aligned.m16n8k16.row.col.f32.bf16.bf16.f32 "
        "{%0,%1,%2,%3}, {%4,%5,%6,%7}, {%8,%9}, {%0,%1,%2,%3};"
        : "+f"(c[0]), "+f"(c[1]), "+f"(c[2]), "+f"(c[3])
        : "r"(a[0]), "r"(a[1]), "r"(a[2]), "r"(a[3]), "r"(b[0]), "r"(b[1]));
}
__device__ __forceinline__ void cpasync16(uint32_t dst, const void* src) {
    asm volatile("cp.async.ca.shared.global [%0], [%1], 16;" :: "r"(dst), "l"(src));
}
#define CP_COMMIT() asm volatile("cp.async.commit_group;" ::: "memory")
#define CP_WAIT0()  asm volatile("cp.async.wait_group 0;" ::: "memory")

// ---------------- conv1 + fused weight packing (tail blocks) ----------------
struct PackArgs {
    const float *w2, *w3, *w4, *wf, *wih, *whh, *pw, *qw;
    __nv_bfloat16 *w2h, *w2l, *w3h, *w3l, *w4h, *w4l, *wfh, *wfl;
    float *wihT, *whhT, *pwT, *qwT;
};
__device__ __forceinline__ void pack_one(const float* w, __nv_bfloat16* bh,
                                         __nv_bfloat16* bl, int idx) {
    float v = w[idx];
    __nv_bfloat16 h, l;
    bsplit(v, h, l);
    bh[idx] = h;
    bl[idx] = l;
}
__global__ void __launch_bounds__(256)
conv1_pack_kernel(const float* __restrict__ in, const float* __restrict__ gW,
                  const float* __restrict__ bias, float* __restrict__ outp,
                  PackArgs pa, int NB1) {
    constexpr int AS = 40, IH = 64, OW = 32, NT = 32, KR = 48, POS = 1024;
    constexpr int WN = NT / 2, NTI = WN / 8, NPAIR = WN / 16;

    if ((int)blockIdx.x >= NB1) {
        // ---- packing tail (float4-packed scan weights) ----
        constexpr int S2 = 64 * 512,     C2 = S2;
        constexpr int S3 = 128 * 1024,   C3 = C2 + S3;
        constexpr int S4 = 256 * 2048,   C4 = C3 + S4;
        constexpr int S5 = 256 * 4096,   C5 = C4 + S5;
        constexpr int S6 = 40 * 384,     C6 = C5 + S6;
        constexpr int S7 = 128 * 384,    C7 = C6 + S7;
        constexpr int S8 = 128 * 64,     C8 = C7 + S8;
        constexpr int S9 = 384 * 64,     C9 = C8 + S9;
        int nb = gridDim.x - NB1;
        for (int idx = ((int)blockIdx.x - NB1) * 256 + threadIdx.x; idx < C9;
             idx += nb * 256) {
            if (idx < C2)      pack_one(pa.w2, pa.w2h, pa.w2l, idx);
            else if (idx < C3) pack_one(pa.w3, pa.w3h, pa.w3l, idx - C2);
            else if (idx < C4) pack_one(pa.w4, pa.w4h, pa.w4l, idx - C3);
            else if (idx < C5) pack_one(pa.wf, pa.wfh, pa.wfl, idx - C4);
            else if (idx < C6) {                 // wihT4: (k4, j, q), k padded to 40
                int t = idx - C5;
                int q = t & 3, j = (t >> 2) % 384, k4 = (t >> 2) / 384;
                int k = 4 * k4 + q;
                pa.wihT[t] = (k < 38) ? pa.wih[(size_t)j * 38 + k] : 0.f;
            } else if (idx < C7) {               // whhT4
                int t = idx - C6;
                int q = t & 3, j = (t >> 2) % 384, k4 = (t >> 2) / 384;
                pa.whhT[t] = pa.whh[(size_t)j * 128 + 4 * k4 + q];
            } else if (idx < C8) {               // pwT4
                int t = idx - C7;
                int q = t & 3, j = (t >> 2) % 64, k4 = (t >> 2) / 64;
                pa.pwT[t] = pa.pw[(size_t)j * 128 + 4 * k4 + q];
            } else {                             // qwT4
                int t = idx - C8;
                int q = t & 3, j = (t >> 2) % 64, k4 = (t >> 2) / 64;
                pa.qwT[t] = pa.qw[(size_t)j * 384 + 4 * k4 + q];
            }
        }
        return;
    }

    // ---- conv1 GEMM (inline B split, NCH=2) ----
    extern __shared__ __align__(16) char smem[];
    __nv_bfloat16* Ah = (__nv_bfloat16*)smem;
    __nv_bfloat16* Al = Ah + 128 * AS;
    __nv_bfloat16* Bh = Al + 128 * AS;
    __nv_bfloat16* Bl = Bh + NT * AS;

    const uint32_t sb   = smem_u32(smem);
    const uint32_t ah_b = sb;
    const uint32_t al_b = sb + 128 * AS * 2;
    const uint32_t bh_b = sb + 128 * AS * 4;
    const uint32_t bl_b = bh_b + NT * AS * 2;

    const int tid = threadIdx.x, lane = tid & 31, wid = tid >> 5;
    const int wm = wid & 3, wn = wid >> 2;
    const int m0 = blockIdx.x * 128;

    float acc[2][NTI][4];
#pragma unroll
    for (int mt = 0; mt < 2; ++mt)
#pragma unroll
        for (int nt = 0; nt < NTI; ++nt)
#pragma unroll
            for (int q = 0; q < 4; ++q) acc[mt][nt][q] = 0.f;

    const int r  = tid & 127;
    const int kg = tid >> 7;
    const int m  = m0 + r;
    const int fr = m / POS;
    const int pg = m & (POS - 1);
    const int oy = pg / OW, ox = pg & (OW - 1);
    const int iyb = 2 * oy - 1, ixb = 2 * ox - 1;
    const int boc = tid >> 4;
    const int bk2 = (tid & 15) * 2;

    float va[16];
    float wb[4];

    auto GATHER = [&](int ch) {
        const int ic = ch * 2 + kg;
        const bool icok = (ic < 3);
        const float* plane = in + ((size_t)fr * 3 + (icok ? ic : 0)) * IH * IH;
#pragma unroll
        for (int ky = 0; ky < 4; ++ky) {
            int iy = iyb + ky;
            bool yok = icok && iy >= 0 && iy < IH;
            const float* rp = plane + iy * IH;
            va[4 * ky + 0] = (yok && ixb >= 0)     ? rp[ixb]     : 0.f;
            va[4 * ky + 1] = yok                   ? rp[ixb + 1] : 0.f;
            va[4 * ky + 2] = yok                   ? rp[ixb + 2] : 0.f;
            va[4 * ky + 3] = (yok && ixb + 3 < IH) ? rp[ixb + 3] : 0.f;
        }
    };
    auto LDGB = [&](int ch) {
        const int k = ch * 32 + bk2;
#pragma unroll
        for (int g = 0; g < 2; ++g) {
            int oc = boc + 16 * g;
            float2 v = make_float2(0.f, 0.f);
            if (k < KR) v = *(const float2*)&gW[(size_t)oc * KR + k];
            wb[2 * g] = v.x; wb[2 * g + 1] = v.y;
        }
    };
    auto STOREA = [&]() {
        uint32_t hw[8], lw[8];
#pragma unroll
        for (int q = 0; q < 8; ++q) pack2(va[2 * q], va[2 * q + 1], hw[q], lw[q]);
        uint32_t dof = r * AS + kg * 16;
        *(uint4*)&Ah[dof]     = *(uint4*)&hw[0];
        *(uint4*)&Ah[dof + 8] = *(uint4*)&hw[4];
        *(uint4*)&Al[dof]     = *(uint4*)&lw[0];
        *(uint4*)&Al[dof + 8] = *(uint4*)&lw[4];
    };
    auto STSB = [&]() {
#pragma unroll
        for (int g = 0; g < 2; ++g) {
            int oc = boc + 16 * g;
            uint32_t hw_, lw_;
            pack2(wb[2 * g], wb[2 * g + 1], hw_, lw_);
            ((uint32_t*)Bh)[oc * 20 + (bk2 >> 1)] = hw_;
            ((uint32_t*)Bl)[oc * 20 + (bk2 >> 1)] = lw_;
        }
    };

    GATHER(0); LDGB(0);
    STOREA(); STSB();
    GATHER(1); LDGB(1);
    __syncthreads();

    for (int ch = 0; ch < 2; ++ch) {
#pragma unroll
        for (int ks = 0; ks < 32; ks += 16) {
            uint32_t ahf[2][4], alf[2][4];
#pragma unroll
            for (int mt = 0; mt < 2; ++mt) {
                int row = wm * 32 + mt * 16 + (lane & 15);
                int koff = ks + ((lane >> 4) << 3);
                uint32_t off = (uint32_t)(row * AS + koff) * 2;
                ldmx4(ahf[mt], ah_b + off);
                ldmx4(alf[mt], al_b + off);
            }
#pragma unroll
            for (int np = 0; np < NPAIR; ++np) {
                uint32_t bhf[4], blf[4];
                int n = wn * WN + np * 16 + (lane & 7) + ((lane >> 4) << 3);
                int koff = ks + (((lane >> 3) & 1) << 3);
                uint32_t off = (uint32_t)(n * AS + koff) * 2;
                ldmx4(bhf, bh_b + off);
                ldmx4(blf, bl_b + off);
#pragma unroll
                for (int s = 0; s < 2; ++s) {
                    int nt = np * 2 + s;
#pragma unroll
                    for (int mt = 0; mt < 2; ++mt) {
                        mma16816(acc[mt][nt], ahf[mt], bhf + 2 * s);
                        mma16816(acc[mt][nt], ahf[mt], blf + 2 * s);
                        mma16816(acc[mt][nt], alf[mt], bhf + 2 * s);
                    }
                }
            }
        }
        __syncthreads();
        if (ch == 0) { STOREA(); STSB(); __syncthreads(); }
    }

#pragma unroll
    for (int mt = 0; mt < 2; ++mt) {
#pragma unroll
        for (int nt = 0; nt < NTI; ++nt) {
            int oc = wn * WN + nt * 8 + 2 * (lane & 3);
            float b0 = bias[oc], b1 = bias[oc + 1];
#pragma unroll
            for (int half = 0; half < 2; ++half) {
                int mm = m0 + wm * 32 + mt * 16 + (lane >> 2) + half * 8;
                int frr = mm / POS;
                int pgg = mm & (POS - 1);
                size_t base = ((size_t)frr * 32 + oc) * POS + pgg;
                outp[base]       = fmaxf(acc[mt][nt][2 * half]     + b0, 0.f);
                outp[base + POS] = fmaxf(acc[mt][nt][2 * half + 1] + b1, 0.f);
            }
        }
    }
}

// ---------------- pipelined tensor-core im2col GEMM (prepacked B) ----
template <int ICR, int IH, int OC, int KTOT, int NT, bool IM2COL, bool RELU, int POS>
__global__ void __launch_bounds__(256)
mmagemm_kernel(const float* __restrict__ in, const __nv_bfloat16* __restrict__ gBh,
               const __nv_bfloat16* __restrict__ gBl, const float* __restrict__ bias,
               float* __restrict__ outp) {
    constexpr int AS  = 40;
    constexpr int OW  = IH / 2;
    constexpr int WN  = NT / 2;
    constexpr int NTI = WN / 8;
    constexpr int NPAIR = WN / 16;
    constexpr int NCH = KTOT / 32;
    constexpr uint32_t BBUF = NT * AS * 2 * 2;

    extern __shared__ __align__(16) char smem[];
    __nv_bfloat16* Ah = (__nv_bfloat16*)smem;
    __nv_bfloat16* Al = Ah + 128 * AS;

    const uint32_t sb   = smem_u32(smem);
    const uint32_t ah_b = sb;
    const uint32_t al_b = sb + 128 * AS * 2;
    const uint32_t bbase = sb + 128 * AS * 4;

    const int tid = threadIdx.x, lane = tid & 31, wid = tid >> 5;
    const int wm = wid & 3, wn = wid >> 2;
    const int m0 = blockIdx.x * 128;
    const int n0g = blockIdx.y * NT;

    float acc[2][NTI][4];
#pragma unroll
    for (int mt = 0; mt < 2; ++mt)
#pragma unroll
        for (int nt = 0; nt < NTI; ++nt)
#pragma unroll
            for (int q = 0; q < 4; ++q) acc[mt][nt][q] = 0.f;

    const int r  = tid & 127;
    const int kg = tid >> 7;
    const int m  = m0 + r;
    const int fr = m / POS;
    const int pg = m & (POS - 1);
    const int oy = pg / OW, ox = pg & (OW - 1);
    const int iyb = 2 * oy - 1, ixb = 2 * ox - 1;

    float va[16];

    auto GATHER = [&](int ch) {
        if (IM2COL) {
            const int ic = ch * 2 + kg;
            const bool icok = (ic < ICR);
            const float* plane = in + ((size_t)fr * ICR + (icok ? ic : 0)) * IH * IH;
#pragma unroll
            for (int ky = 0; ky < 4; ++ky) {
                int iy = iyb + ky;
                bool yok = icok && iy >= 0 && iy < IH;
                const float* rp = plane + iy * IH;
                va[4 * ky + 0] = (yok && ixb >= 0)     ? rp[ixb]     : 0.f;
                va[4 * ky + 1] = yok                   ? rp[ixb + 1] : 0.f;
                va[4 * ky + 2] = yok                   ? rp[ixb + 2] : 0.f;
                va[4 * ky + 3] = (yok && ixb + 3 < IH) ? rp[ixb + 3] : 0.f;
            }
        } else {
            const float* rp = in + (size_t)m * KTOT + ch * 32 + kg * 16;
#pragma unroll
            for (int q = 0; q < 4; ++q) {
                float4 v = *(const float4*)(rp + q * 4);
                va[4 * q + 0] = v.x; va[4 * q + 1] = v.y;
                va[4 * q + 2] = v.z; va[4 * q + 3] = v.w;
            }
        }
    };
    auto STOREA = [&]() {
        uint32_t hw[8], lw[8];
#pragma unroll
        for (int q = 0; q < 8; ++q) pack2(va[2 * q], va[2 * q + 1], hw[q], lw[q]);
        uint32_t dof = r * AS + kg * 16;
        *(uint4*)&Ah[dof]     = *(uint4*)&hw[0];
        *(uint4*)&Ah[dof + 8] = *(uint4*)&hw[4];
        *(uint4*)&Al[dof]     = *(uint4*)&lw[0];
        *(uint4*)&Al[dof + 8] = *(uint4*)&lw[4];
    };
    auto STAGEB = [&](int ch) {
        uint32_t bd = bbase + (ch & 1) * BBUF;
        for (int i = tid; i < NT * 4; i += 256) {
            int n = i >> 2, q = i & 3;
            size_t go = (size_t)(n0g + n) * KTOT + ch * 32 + q * 8;
            cpasync16(bd + n * 80 + q * 16, gBh + go);
            cpasync16(bd + NT * 80 + n * 80 + q * 16, gBl + go);
        }
    };

    GATHER(0);
    STAGEB(0);
    CP_COMMIT();
    STOREA();
    if (NCH > 1) GATHER(1);
    CP_WAIT0();
    __syncthreads();

    for (int ch = 0; ch < NCH; ++ch) {
        if (ch + 1 < NCH) STAGEB(ch + 1);
        CP_COMMIT();

        const uint32_t bh_b = bbase + (ch & 1) * BBUF;
        const uint32_t bl_b = bh_b + NT * 80;
#pragma unroll
        for (int ks = 0; ks < 32; ks += 16) {
            uint32_t ahf[2][4], alf[2][4];
#pragma unroll
            for (int mt = 0; mt < 2; ++mt) {
                int row = wm * 32 + mt * 16 + (lane & 15);
                int koff = ks + ((lane >> 4) << 3);
                uint32_t off = (uint32_t)(row * AS + koff) * 2;
                ldmx4(ahf[mt], ah_b + off);
                ldmx4(alf[mt], al_b + off);
            }
#pragma unroll
            for (int np = 0; np < NPAIR; ++np) {
                uint32_t bhf[4], blf[4];
                int n = wn * WN + np * 16 + (lane & 7) + ((lane >> 4) << 3);
                int koff = ks + (((lane >> 3) & 1) << 3);
                uint32_t off = (uint32_t)(n * AS + koff) * 2;
                ldmx4(bhf, bh_b + off);
                ldmx4(blf, bl_b + off);
#pragma unroll
                for (int s = 0; s < 2; ++s) {
                    int nt = np * 2 + s;
#pragma unroll
                    for (int mt = 0; mt < 2; ++mt) {
                        mma16816(acc[mt][nt], ahf[mt], bhf + 2 * s);
                        mma16816(acc[mt][nt], ahf[mt], blf + 2 * s);
                        mma16816(acc[mt][nt], alf[mt], bhf + 2 * s);
                    }
                }
            }
        }
        __syncthreads();
        if (ch + 1 < NCH) {
            STOREA();
            if (ch + 2 < NCH) GATHER(ch + 2);
            CP_WAIT0();
            __syncthreads();
        }
    }

#pragma unroll
    for (int mt = 0; mt < 2; ++mt) {
#pragma unroll
        for (int nt = 0; nt < NTI; ++nt) {
            int oc = n0g + wn * WN + nt * 8 + 2 * (lane & 3);
            float b0 = bias[oc], b1 = bias[oc + 1];
#pragma unroll
            for (int half = 0; half < 2; ++half) {
                int mm = m0 + wm * 32 + mt * 16 + (lane >> 2) + half * 8;
                float x0 = acc[mt][nt][2 * half]     + b0;
                float x1 = acc[mt][nt][2 * half + 1] + b1;
                if (RELU) { x0 = fmaxf(x0, 0.f); x1 = fmaxf(x1, 0.f); }
                if (IM2COL) {
                    int frr = mm / POS;
                    int pgg = mm & (POS - 1);
                    size_t base = ((size_t)frr * OC + oc) * POS + pgg;
                    outp[base]       = x0;
                    outp[base + POS] = x1;
                } else {
                    *(float2*)&outp[(size_t)mm * OC + oc] = make_float2(x0, x1);
                }
            }
        }
    }
}

// ---------------- sequential scan: float4-packed transposed weights ----------------
__global__ void scan_kernel(const float* __restrict__ actions, const float* __restrict__ feats,
                            const float* __restrict__ wihT, const float* __restrict__ whhT,
                            const float* __restrict__ bih, const float* __restrict__ bhh,
                            const float* __restrict__ pwT, const float* __restrict__ pb,
                            const float* __restrict__ qwT, const float* __restrict__ qb,
                            const float* __restrict__ eps, float* __restrict__ out) {
    int b = blockIdx.x, tid = threadIdx.x;
    __shared__ float x_s[40];
    __shared__ __align__(16) float h_s[HH];
    __shared__ __align__(16) float f_s[FD];
    __shared__ float gi_s[3 * HH], gh_s[3 * HH];
    __shared__ float p_s[2 * LL], q_s[2 * LL];

    if (tid < 40) x_s[tid] = 0.f;        // includes pad slots 38,39
    if (tid < HH) h_s[tid] = 0.f;

    const float bih_j = bih[tid];
    const float bhh_j = bhh[tid];

    const float4* wihT4 = (const float4*)wihT;
    const float4* whhT4 = (const float4*)whhT;
    const float4* pwT4  = (const float4*)pwT;
    const float4* qwT4  = (const float4*)qwT;

    float* out_mup = out;
    float* out_lvp = out + (size_t)NFR * LL;
    float* out_muq = out + (size_t)NFR * LL * 2;
    float* out_lvq = out + (size_t)NFR * LL * 3;
    float* out_h   = out + (size_t)NFR * LL * 4;
    float* out_z   = out + (size_t)NFR * LL * 4 + (size_t)NFR * HH;

    for (int t = 0; t < TT; ++t) {
        int bt = b * TT + t;
        if (tid >= LL && tid < LL + AA) x_s[tid] = actions[(size_t)bt * AA + (tid - LL)];
        if (tid < FD) f_s[tid] = feats[(size_t)bt * FD + tid];
        __syncthreads();

        {
            const int j = tid;
            float a0 = 0.f, a1 = 0.f, a2 = 0.f, a3 = 0.f;
#pragma unroll
            for (int k4 = 0; k4 < 10; ++k4) {
                float4 w = wihT4[k4 * 384 + j];
                a0 = fmaf(x_s[4 * k4 + 0], w.x, a0);
                a1 = fmaf(x_s[4 * k4 + 1], w.y, a1);
                a2 = fmaf(x_s[4 * k4 + 2], w.z, a2);
                a3 = fmaf(x_s[4 * k4 + 3], w.w, a3);
            }
            float g0 = 0.f, g1 = 0.f, g2 = 0.f, g3 = 0.f;
#pragma unroll
            for (int k4 = 0; k4 < 32; ++k4) {
                float4 w = whhT4[k4 * 384 + j];
                g0 = fmaf(h_s[4 * k4 + 0], w.x, g0);
                g1 = fmaf(h_s[4 * k4 + 1], w.y, g1);
                g2 = fmaf(h_s[4 * k4 + 2], w.z, g2);
                g3 = fmaf(h_s[4 * k4 + 3], w.w, g3);
            }
            gi_s[j] = bih_j + (a0 + a1) + (a2 + a3);
            gh_s[j] = bhh_j + (g0 + g1) + (g2 + g3);
        }
        __syncthreads();

        if (tid < HH) {
            int u = tid;
            float r  = 1.f / (1.f + expf(-(gi_s[u] + gh_s[u])));
            float zz = 1.f / (1.f + expf(-(gi_s[u + HH] + gh_s[u + HH])));
            float nn = tanhf(gi_s[u + 2 * HH] + r * gh_s[u + 2 * HH]);
            h_s[u] = (1.f - zz) * nn + zz * h_s[u];
        }
        __syncthreads();

        if (tid < 2 * LL) {
            const int j = tid;
            float g0 = 0.f, g1 = 0.f, g2 = 0.f, g3 = 0.f;
#pragma unroll
            for (int k4 = 0; k4 < 32; ++k4) {
                float4 w = pwT4[k4 * 64 + j];
                g0 = fmaf(h_s[4 * k4 + 0], w.x, g0);
                g1 = fmaf(h_s[4 * k4 + 1], w.y, g1);
                g2 = fmaf(h_s[4 * k4 + 2], w.z, g2);
                g3 = fmaf(h_s[4 * k4 + 3], w.w, g3);
            }
            p_s[j] = pb[j] + (g0 + g1) + (g2 + g3);
        } else if (tid < 4 * LL) {
            const int j = tid - 2 * LL;
            float g0 = 0.f, g1 = 0.f, g2 = 0.f, g3 = 0.f;
#pragma unroll
            for (int k4 = 0; k4 < 32; ++k4) {
                float4 w = qwT4[k4 * 64 + j];
                g0 = fmaf(h_s[4 * k4 + 0], w.x, g0);
                g1 = fmaf(h_s[4 * k4 + 1], w.y, g1);
                g2 = fmaf(h_s[4 * k4 + 2], w.z, g2);
                g3 = fmaf(h_s[4 * k4 + 3], w.w, g3);
            }
#pragma unroll
            for (int k4 = 0; k4 < 64; ++k4) {
                float4 w = qwT4[(32 + k4) * 64 + j];
                g0 = fmaf(f_s[4 * k4 + 0], w.x, g0);
                g1 = fmaf(f_s[4 * k4 + 1], w.y, g1);
                g2 = fmaf(f_s[4 * k4 + 2], w.z, g2);
                g3 = fmaf(f_s[4 * k4 + 3], w.w, g3);
            }
            q_s[j] = qb[j] + (g0 + g1) + (g2 + g3);
        }
        __syncthreads();

        if (tid < HH) out_h[(size_t)bt * HH + tid] = h_s[tid];
        if (tid < LL) {
            int l = tid;
            out_mup[(size_t)bt * LL + l] = p_s[l];
            out_lvp[(size_t)bt * LL + l] = p_s[l + LL];
            float muq = q_s[l], lvq = q_s[l + LL];
            out_muq[(size_t)bt * LL + l] = muq;
            out_lvq[(size_t)bt * LL + l] = lvq;
            float z = muq + expf(0.5f * lvq) * eps[(size_t)bt * LL + l];
            out_z[(size_t)bt * LL + l] = z;
            x_s[l] = z;
        }
        __syncthreads();
    }
}

// ---------------- launch ----------------
extern "C" void kernel_launch(void* const* d_in, const int* in_sizes, int n_in,
                              void* d_out, int out_size) {
    const float* states  = (const float*)d_in[0];
    const float* actions = (const float*)d_in[1];
    const float* c1_w = (const float*)d_in[2];
    const float* c1_b = (const float*)d_in[3];
    const float* c2_w = (const float*)d_in[4];
    const float* c2_b = (const float*)d_in[5];
    const float* c3_w = (const float*)d_in[6];
    const float* c3_b = (const float*)d_in[7];
    const float* c4_w = (const float*)d_in[8];
    const float* c4_b = (const float*)d_in[9];
    const float* fc_w = (const float*)d_in[10];
    const float* fc_b = (const float*)d_in[11];
    const float* gru_wih = (const float*)d_in[12];
    const float* gru_whh = (const float*)d_in[13];
    const float* gru_bih = (const float*)d_in[14];
    const float* gru_bhh = (const float*)d_in[15];
    const float* prior_w = (const float*)d_in[16];
    const float* prior_b = (const float*)d_in[17];
    const float* post_w  = (const float*)d_in[18];
    const float* post_b  = (const float*)d_in[19];
    const float* eps     = (const float*)d_in[20];
    float* out = (float*)d_out;

    float *b1, *b2, *b3, *b4, *feats, *wihT, *whhT, *pwT, *qwT;
    __nv_bfloat16 *w2h, *w2l, *w3h, *w3l, *w4h, *w4l, *wfh, *wfl;
    cudaGetSymbolAddress((void**)&b1, g_b1);
    cudaGetSymbolAddress((void**)&b2, g_b2);
    cudaGetSymbolAddress((void**)&b3, g_b3);
    cudaGetSymbolAddress((void**)&b4, g_b4);
    cudaGetSymbolAddress((void**)&feats, g_feats);
    cudaGetSymbolAddress((void**)&w2h, g_w2h);  cudaGetSymbolAddress((void**)&w2l, g_w2l);
    cudaGetSymbolAddress((void**)&w3h, g_w3h);  cudaGetSymbolAddress((void**)&w3l, g_w3l);
    cudaGetSymbolAddress((void**)&w4h, g_w4h);  cudaGetSymbolAddress((void**)&w4l, g_w4l);
    cudaGetSymbolAddress((void**)&wfh, g_wfh);  cudaGetSymbolAddress((void**)&wfl, g_wfl);
    cudaGetSymbolAddress((void**)&wihT, g_wihT);
    cudaGetSymbolAddress((void**)&whhT, g_whhT);
    cudaGetSymbolAddress((void**)&pwT, g_pwT);
    cudaGetSymbolAddress((void**)&qwT, g_qwT);

    auto c2 = mmagemm_kernel<32, 32, 64, 512, 64, true, true, 256>;
    auto c3 = mmagemm_kernel<64, 16, 128, 1024, 128, true, true, 64>;
    auto c4 = mmagemm_kernel<128, 8, 256, 2048, 128, true, true, 16>;
    auto fc = mmagemm_kernel<1, 2, 256, 4096, 32, false, false, 1>;
    const int smA  = 128 * 40 * 2 * 2;                 // 20480
    const int sm1 = smA + 32 * 40 * 2 * 2;             // 25600
    const int sm2 = smA + 2 * 64 * 40 * 2 * 2;         // 40960
    const int sm3 = smA + 2 * 128 * 40 * 2 * 2;        // 61440
    const int smf = smA + 2 * 32 * 40 * 2 * 2;         // 30720
    cudaFuncSetAttribute(conv1_pack_kernel, cudaFuncAttributeMaxDynamicSharedMemorySize, sm1);
    cudaFuncSetAttribute(c2, cudaFuncAttributeMaxDynamicSharedMemorySize, sm2);
    cudaFuncSetAttribute(c3, cudaFuncAttributeMaxDynamicSharedMemorySize, sm3);
    cudaFuncSetAttribute(c4, cudaFuncAttributeMaxDynamicSharedMemorySize, sm3);
    cudaFuncSetAttribute(fc, cudaFuncAttributeMaxDynamicSharedMemorySize, smf);

    PackArgs pa;
    pa.w2 = c2_w; pa.w3 = c3_w; pa.w4 = c4_w; pa.wf = fc_w;
    pa.wih = gru_wih; pa.whh = gru_whh; pa.pw = prior_w; pa.qw = post_w;
    pa.w2h = w2h; pa.w2l = w2l; pa.w3h = w3h; pa.w3l = w3l;
    pa.w4h = w4h; pa.w4l = w4l; pa.wfh = wfh; pa.wfl = wfl;
    pa.wihT = wihT; pa.whhT = whhT; pa.pwT = pwT; pa.qwT = qwT;

    // 0: conv1 GEMM (inline B) + weight packing tail blocks
    conv1_pack_kernel<<<16384 + 1024, 256, sm1>>>(states, c1_w, c1_b, b1, pa, 16384);
    // 1: conv2 GEMM (M=524288, N=64, K=512)
    c2<<<dim3(4096, 1), 256, sm2>>>(b1, w2h, w2l, c2_b, b2);
    // 2: conv3 GEMM (M=131072, N=128, K=1024)
    c3<<<dim3(1024, 1), 256, sm3>>>(b2, w3h, w3l, c3_b, b3);
    // 3 <- profiled: conv4 GEMM (M=32768, N=256, K=2048)
    c4<<<dim3(256, 2), 256, sm3>>>(b3, w4h, w4l, c4_b, b4);
    // 4: fc GEMM (M=2048, N=256, K=4096) — NT=32, grid (16,8)
    fc<<<dim3(16, 8), 256, smf>>>(b4, wfh, wfl, fc_b, feats);
    // 5: scan (float4-packed transposed weights)
    scan_kernel<<<BB, 384>>>(actions, feats, wihT, whhT, gru_bih, gru_bhh,
                             pwT, prior_b, qwT, post_b, eps, out);
}